// round 8
// baseline (speedup 1.0000x reference)
#include <cuda_runtime.h>
#include <cuda_fp16.h>
#include <cstdint>

// Problem constants
#define NN 100000
#define EE 1600000
#define GGR 64

// ---------------- static device scratch ----------------
__device__ float    g_qkvs[(size_t)NN * 512]; // q[0:128) (k/v fp32 slots unused) skip[384:512)
__device__ __half   g_kv16[(size_t)NN * 256]; // per node: k[0:128) v[128:256) fp16
__device__ float    g_h   [(size_t)NN * 128];
__device__ float    g_gh  [(size_t)NN * 128];
__device__ float    g_gate[NN];
__device__ float    g_pool[GGR * 128];
__device__ float    g_gs[GGR];
__device__ __half   g_Wh1[512 * 128];         // layer-1 packed fp16 weights
__device__ __half   g_Wh2[512 * 128];         // layer-2 packed fp16 weights
__device__ __half   g_Whg[128 * 128];         // gate packed fp16 weights
__device__ float    g_B1[512];
__device__ float    g_B2[512];
__device__ float    g_Bg[128];
// CSR (dst-sorted adjacency)
__device__ int      g_off[NN + 1];
__device__ int      g_cur[NN];
__device__ int      g_csrc[EE];
__device__ int      g_bsums[512];

// ---------------- fp16 mma ----------------
__device__ __forceinline__ void mma16(float* d, const uint32_t* a, const uint32_t* b) {
    asm volatile("mma.sync.aligned.m16n8k16.row.col.f32.f16.f16.f32 "
        "{%0,%1,%2,%3}, {%4,%5,%6,%7}, {%8,%9}, {%0,%1,%2,%3};"
        : "+f"(d[0]), "+f"(d[1]), "+f"(d[2]), "+f"(d[3])
        : "r"(a[0]), "r"(a[1]), "r"(a[2]), "r"(a[3]), "r"(b[0]), "r"(b[1]));
}

// ---------------- weight packing (fp16) ----------------
__global__ void pack4(const float* __restrict__ wq, const float* __restrict__ bq,
                      const float* __restrict__ wk, const float* __restrict__ bk,
                      const float* __restrict__ wv, const float* __restrict__ bv,
                      const float* __restrict__ ws, const float* __restrict__ bs,
                      __half* __restrict__ Wh, float* __restrict__ B) {
    int idx = blockIdx.x * blockDim.x + threadIdx.x;
    if (idx < 512 * 128) {
        int orow = idx >> 7, k = idx & 127;
        int sel = orow >> 7, r = orow & 127;
        const float* w = (sel == 0) ? wq : (sel == 1) ? wk : (sel == 2) ? wv : ws;
        Wh[idx] = __float2half_rn(w[r * 128 + k]);
    }
    if (idx < 512) {
        int sel = idx >> 7, r = idx & 127;
        const float* b = (sel == 0) ? bq : (sel == 1) ? bk : (sel == 2) ? bv : bs;
        B[idx] = b[r];
    }
}

__global__ void pack1(const float* __restrict__ w, const float* __restrict__ b,
                      __half* __restrict__ Wh, float* __restrict__ B) {
    int idx = blockIdx.x * blockDim.x + threadIdx.x;
    if (idx < 128 * 128) Wh[idx] = __float2half_rn(w[idx]);
    if (idx < 128) B[idx] = b[idx];
}

// ---------------- fp16 single-pass mma GEMM ----------------
#define KH 136
#define GEMM_SMEM_H ((128 + 64) * KH * 2)        // 52224 B

template<bool RELU, bool WRITEKV>
__global__ __launch_bounds__(256, 2)
void gemm_h(const float* __restrict__ X, int n,
            const __half* __restrict__ Wh, const float* __restrict__ bias,
            float* __restrict__ Y, int OUT) {
    extern __shared__ __half sh[];
    __half* sX = sh;               // [128][KH]
    __half* sW = sh + 128 * KH;    // [64][KH]

    const int tid = threadIdx.x, wid = tid >> 5, lane = tid & 31;
    const int wm = wid & 3, wn = wid >> 2;
    const int row0 = blockIdx.x * 128, col0 = blockIdx.y * 64;
    const int grp = lane >> 2, tg = lane & 3;

#pragma unroll
    for (int j = 0; j < 8; j++) {
        int idx = tid + 256 * j;
        int r = idx >> 4, c8 = idx & 15;
        int gr = row0 + r;
        float4 v0 = make_float4(0.f, 0.f, 0.f, 0.f);
        float4 v1 = make_float4(0.f, 0.f, 0.f, 0.f);
        if (gr < n) {
            v0 = *(const float4*)(X + (size_t)gr * 128 + c8 * 8);
            v1 = *(const float4*)(X + (size_t)gr * 128 + c8 * 8 + 4);
        }
        __half2 h0 = __floats2half2_rn(v0.x, v0.y);
        __half2 h1 = __floats2half2_rn(v0.z, v0.w);
        __half2 h2 = __floats2half2_rn(v1.x, v1.y);
        __half2 h3 = __floats2half2_rn(v1.z, v1.w);
        uint4 pk;
        pk.x = *(uint32_t*)&h0; pk.y = *(uint32_t*)&h1;
        pk.z = *(uint32_t*)&h2; pk.w = *(uint32_t*)&h3;
        *(uint4*)(sX + r * KH + c8 * 8) = pk;
    }
#pragma unroll
    for (int j = 0; j < 4; j++) {
        int idx = tid + 256 * j;
        int r = idx >> 4, c8 = idx & 15;
        *(uint4*)(sW + r * KH + c8 * 8) =
            *(const uint4*)(Wh + (size_t)(col0 + r) * 128 + c8 * 8);
    }
    __syncthreads();

    float acc[2][4][4];
#pragma unroll
    for (int mt = 0; mt < 2; mt++)
#pragma unroll
        for (int nt = 0; nt < 4; nt++)
#pragma unroll
            for (int q = 0; q < 4; q++) acc[mt][nt][q] = 0.f;

#pragma unroll
    for (int ks = 0; ks < 8; ks++) {
        const int c = ks * 16 + 2 * tg;
        uint32_t a[2][4];
#pragma unroll
        for (int mt = 0; mt < 2; mt++) {
            const int r = wm * 32 + mt * 16 + grp;
            a[mt][0] = *(const uint32_t*)(sX + r * KH + c);
            a[mt][1] = *(const uint32_t*)(sX + (r + 8) * KH + c);
            a[mt][2] = *(const uint32_t*)(sX + r * KH + c + 8);
            a[mt][3] = *(const uint32_t*)(sX + (r + 8) * KH + c + 8);
        }
        uint32_t b[4][2];
#pragma unroll
        for (int nt = 0; nt < 4; nt++) {
            const int nr = wn * 32 + nt * 8 + grp;
            b[nt][0] = *(const uint32_t*)(sW + nr * KH + c);
            b[nt][1] = *(const uint32_t*)(sW + nr * KH + c + 8);
        }
#pragma unroll
        for (int mt = 0; mt < 2; mt++)
#pragma unroll
            for (int nt = 0; nt < 4; nt++) mma16(acc[mt][nt], a[mt], b[nt]);
    }

#pragma unroll
    for (int mt = 0; mt < 2; mt++) {
        const int gr = row0 + wm * 32 + mt * 16 + grp;
#pragma unroll
        for (int nt = 0; nt < 4; nt++) {
            const int col = col0 + wn * 32 + nt * 8 + 2 * tg;
            const float b0 = bias[col], b1 = bias[col + 1];
            float2 o1 = make_float2(acc[mt][nt][0] + b0, acc[mt][nt][1] + b1);
            float2 o2 = make_float2(acc[mt][nt][2] + b0, acc[mt][nt][3] + b1);
            if (RELU) {
                o1.x = fmaxf(o1.x, 0.f); o1.y = fmaxf(o1.y, 0.f);
                o2.x = fmaxf(o2.x, 0.f); o2.y = fmaxf(o2.y, 0.f);
            }
            const bool mid = WRITEKV && (col >= 128 && col < 384);
            if (!mid) {
                if (gr < n)     *(float2*)(Y + (size_t)gr * OUT + col) = o1;
                if (gr + 8 < n) *(float2*)(Y + (size_t)(gr + 8) * OUT + col) = o2;
            } else {
                // k/v go ONLY to the fp16 record (fp32 slots never read)
                if (gr < n)
                    *(__half2*)(g_kv16 + (size_t)gr * 256 + (col - 128)) =
                        __floats2half2_rn(o1.x, o1.y);
                if (gr + 8 < n)
                    *(__half2*)(g_kv16 + (size_t)(gr + 8) * 256 + (col - 128)) =
                        __floats2half2_rn(o2.x, o2.y);
            }
        }
    }
}

// ================= CSR build =================
__global__ void hist_zero(int n) {
    int i = blockIdx.x * blockDim.x + threadIdx.x;
    if (i < n) g_cur[i] = 0;
}
__global__ void hist(const int* __restrict__ dst, int E) {
    int e = blockIdx.x * blockDim.x + threadIdx.x;
    if (e < E) atomicAdd(&g_cur[dst[e]], 1);
}
__global__ void scan_blocks(int n) {
    __shared__ int sm[256];
    int t = threadIdx.x;
    int i = blockIdx.x * 256 + t;
    int v = (i < n) ? g_cur[i] : 0;
    sm[t] = v;
    __syncthreads();
#pragma unroll
    for (int o = 1; o < 256; o <<= 1) {
        int x = (t >= o) ? sm[t - o] : 0;
        __syncthreads();
        sm[t] += x;
        __syncthreads();
    }
    if (i < n) g_off[i] = sm[t] - v;
    if (t == 255) g_bsums[blockIdx.x] = sm[255];
}
__global__ void scan_tops(int nblk) {
    __shared__ int sm[512];
    int t = threadIdx.x;
    int v = (t < nblk) ? g_bsums[t] : 0;
    sm[t] = v;
    __syncthreads();
#pragma unroll
    for (int o = 1; o < 512; o <<= 1) {
        int x = (t >= o) ? sm[t - o] : 0;
        __syncthreads();
        sm[t] += x;
        __syncthreads();
    }
    if (t < nblk) g_bsums[t] = sm[t] - v;
}
__global__ void scan_add(int n, int E) {
    int i = blockIdx.x * 256 + threadIdx.x;
    if (i < n) {
        int o = g_off[i] + g_bsums[blockIdx.x];
        g_off[i] = o;
        g_cur[i] = o;
    }
    if (i == 0) g_off[n] = E;
}
__global__ void fill_csr(const int* __restrict__ src, const int* __restrict__ dst, int E) {
    int e = blockIdx.x * blockDim.x + threadIdx.x;
    if (e >= E) return;
    int p = atomicAdd(&g_cur[dst[e]], 1);
    g_csrc[p] = src[e];
}

// ================= fused per-node attention: 2 warps/node =================
// Each warp handles a contiguous half of the node's edge list; partial
// acc/sum combined through shared memory; warp 0 writes the output.
__global__ __launch_bounds__(256, 8)
void node_attn(int n) {
    __shared__ float sacc[4][128];
    __shared__ float ssum[4];

    const int wid = threadIdx.x >> 5, lane = threadIdx.x & 31;
    const int local = wid >> 1;                 // node slot in block: 0..3
    const int sub = wid & 1;                    // which half of edges
    const int node = blockIdx.x * 4 + local;
    if (node >= n) { __syncthreads(); return; }

    const float scale = 0.08838834764831845f;   // 1/sqrt(128)
    const float* base = g_qkvs + (size_t)node * 512;
    float4 q = *(const float4*)(base + lane * 4);
    q.x *= scale; q.y *= scale; q.z *= scale; q.w *= scale;

    const int beg = g_off[node], end = g_off[node + 1];
    const int cnt = end - beg;
    const int half = (cnt + 1) >> 1;
    int j   = beg + sub * half;
    int jend = sub ? end : beg + half;

    float4 acc = make_float4(0.f, 0.f, 0.f, 0.f);
    float sum = 0.f;

    for (; j + 4 <= jend; j += 4) {
        const __half* r[4];
        float d[4];
#pragma unroll
        for (int u = 0; u < 4; u++) r[u] = g_kv16 + (size_t)g_csrc[j + u] * 256;
#pragma unroll
        for (int u = 0; u < 4; u++) {
            uint2 kk = *(const uint2*)(r[u] + lane * 4);
            float2 a = __half22float2(*(const __half2*)&kk.x);
            float2 b = __half22float2(*(const __half2*)&kk.y);
            d[u] = q.x * a.x + q.y * a.y + q.z * b.x + q.w * b.y;
        }
#pragma unroll
        for (int o = 16; o; o >>= 1) {
#pragma unroll
            for (int u = 0; u < 4; u++) d[u] += __shfl_xor_sync(0xffffffffu, d[u], o);
        }
        float e[4];
#pragma unroll
        for (int u = 0; u < 4; u++) e[u] = __expf(d[u]);
#pragma unroll
        for (int u = 0; u < 4; u++) {
            uint2 vv = *(const uint2*)(r[u] + 128 + lane * 4);
            float2 va = __half22float2(*(const __half2*)&vv.x);
            float2 vb = __half22float2(*(const __half2*)&vv.y);
            acc.x += e[u] * va.x; acc.y += e[u] * va.y;
            acc.z += e[u] * vb.x; acc.w += e[u] * vb.y;
            sum += e[u];
        }
    }
    for (; j < jend; j++) {
        const __half* r0 = g_kv16 + (size_t)g_csrc[j] * 256;
        uint2 kk = *(const uint2*)(r0 + lane * 4);
        float2 a = __half22float2(*(const __half2*)&kk.x);
        float2 b = __half22float2(*(const __half2*)&kk.y);
        float d0 = q.x * a.x + q.y * a.y + q.z * b.x + q.w * b.y;
#pragma unroll
        for (int o = 16; o; o >>= 1) d0 += __shfl_xor_sync(0xffffffffu, d0, o);
        float e0 = __expf(d0);
        uint2 vv = *(const uint2*)(r0 + 128 + lane * 4);
        float2 va = __half22float2(*(const __half2*)&vv.x);
        float2 vb = __half22float2(*(const __half2*)&vv.y);
        acc.x += e0 * va.x; acc.y += e0 * va.y;
        acc.z += e0 * vb.x; acc.w += e0 * vb.y;
        sum += e0;
    }

    // combine halves through smem
    if (sub == 1) {
        *(float4*)(&sacc[local][lane * 4]) = acc;
        if (lane == 0) ssum[local] = sum;
    }
    __syncthreads();
    if (sub == 0) {
        float4 p = *(const float4*)(&sacc[local][lane * 4]);
        acc.x += p.x; acc.y += p.y; acc.z += p.z; acc.w += p.w;
        sum += ssum[local];

        float inv = (cnt > 0) ? (1.f / sum) : 0.f;
        float4 skip = *(const float4*)(base + 384 + lane * 4);
        float4 o;
        o.x = fmaxf(acc.x * inv + skip.x, 0.f);
        o.y = fmaxf(acc.y * inv + skip.y, 0.f);
        o.z = fmaxf(acc.z * inv + skip.z, 0.f);
        o.w = fmaxf(acc.w * inv + skip.w, 0.f);
        *(float4*)(g_h + (size_t)node * 128 + lane * 4) = o;
    }
}

// ---------------- graph-level ----------------
__global__ void init_graph() {
    int i = blockIdx.x * blockDim.x + threadIdx.x;
    if (i < GGR * 128) g_pool[i] = 0.f;
    if (i < GGR) g_gs[i] = 0.f;
}

__global__ void gate_dot(const float* __restrict__ gw2, const float* __restrict__ gb2,
                         const int* __restrict__ batch, int n) {
    int w = (blockIdx.x * blockDim.x + threadIdx.x) >> 3;
    int t = threadIdx.x & 7;
    if (w >= n) return;
    const float* hp = g_gh + (size_t)w * 128;
    float dot = 0.f;
#pragma unroll
    for (int i = 0; i < 4; i++) {
        float4 a = *(const float4*)(hp + (t + 8 * i) * 4);
        float4 b = *(const float4*)(gw2 + (t + 8 * i) * 4);
        dot += a.x * b.x + a.y * b.y + a.z * b.z + a.w * b.w;
    }
#pragma unroll
    for (int o = 4; o; o >>= 1) dot += __shfl_xor_sync(0xffffffffu, dot, o);
    if (t == 0) {
        float ev = __expf(dot + gb2[0]);
        g_gate[w] = ev;
        atomicAdd(&g_gs[batch[w]], ev);
    }
}

#define POOL_CHUNK 512
__global__ void pool_kernel(const int* __restrict__ batch, int n) {
    int d = threadIdx.x;
    int n0 = blockIdx.x * POOL_CHUNK;
    int n1 = min(n0 + POOL_CHUNK, n);
    if (n0 >= n) return;
    int curb = batch[n0];
    float acc = 0.f;
    for (int node = n0; node < n1; node++) {
        int b = batch[node];
        if (b != curb) {
            atomicAdd(&g_pool[curb * 128 + d], acc);
            acc = 0.f; curb = b;
        }
        float wgt = g_gate[node] / g_gs[b];
        acc += wgt * g_h[(size_t)node * 128 + d];
    }
    atomicAdd(&g_pool[curb * 128 + d], acc);
}

__global__ void classifier(const float* __restrict__ cw, const float* __restrict__ cb,
                           float* __restrict__ out) {
    int i = threadIdx.x;
    if (i >= GGR * 10) return;
    int g = i / 10, c = i % 10;
    float a = cb[c];
#pragma unroll 16
    for (int k = 0; k < 128; k++) a += g_pool[g * 128 + k] * cw[c * 128 + k];
    out[i] = a;
}

// ---------------- host orchestration ----------------
extern "C" void kernel_launch(void* const* d_in, const int* in_sizes, int n_in,
                              void* d_out, int out_size) {
    const float* x   = (const float*)d_in[0];
    const int* eidx  = (const int*)d_in[1];
    const int* batch = (const int*)d_in[2];
    const float *wq1 = (const float*)d_in[3],  *bq1 = (const float*)d_in[4];
    const float *wk1 = (const float*)d_in[5],  *bk1 = (const float*)d_in[6];
    const float *wv1 = (const float*)d_in[7],  *bv1 = (const float*)d_in[8];
    const float *ws1 = (const float*)d_in[9],  *bs1 = (const float*)d_in[10];
    const float *wq2 = (const float*)d_in[11], *bq2 = (const float*)d_in[12];
    const float *wk2 = (const float*)d_in[13], *bk2 = (const float*)d_in[14];
    const float *wv2 = (const float*)d_in[15], *bv2 = (const float*)d_in[16];
    const float *ws2 = (const float*)d_in[17], *bs2 = (const float*)d_in[18];
    const float *gw1 = (const float*)d_in[19], *gb1 = (const float*)d_in[20];
    const float *gw2 = (const float*)d_in[21], *gb2 = (const float*)d_in[22];
    const float *cw  = (const float*)d_in[23], *cb  = (const float*)d_in[24];
    float* out = (float*)d_out;

    const int n = in_sizes[0] / 128;
    const int E = in_sizes[1] / 2;
    const int* src = eidx;
    const int* dst = eidx + E;

    static float* p_qkvs = nullptr; static float* p_h = nullptr; static float* p_gh = nullptr;
    static __half *p_Wh1 = nullptr, *p_Wh2 = nullptr, *p_Whg = nullptr;
    static float  *p_B1 = nullptr,  *p_B2 = nullptr,  *p_Bg = nullptr;
    static cudaStream_t s1 = nullptr, s2 = nullptr;
    static cudaEvent_t evFork = nullptr, evCsr = nullptr, evPack = nullptr, evInitG = nullptr;
    if (!p_qkvs) {
        cudaGetSymbolAddress((void**)&p_qkvs, g_qkvs);
        cudaGetSymbolAddress((void**)&p_h,    g_h);
        cudaGetSymbolAddress((void**)&p_gh,   g_gh);
        cudaGetSymbolAddress((void**)&p_Wh1,  g_Wh1);
        cudaGetSymbolAddress((void**)&p_Wh2,  g_Wh2);
        cudaGetSymbolAddress((void**)&p_Whg,  g_Whg);
        cudaGetSymbolAddress((void**)&p_B1,   g_B1);
        cudaGetSymbolAddress((void**)&p_B2,   g_B2);
        cudaGetSymbolAddress((void**)&p_Bg,   g_Bg);
        cudaFuncSetAttribute((const void*)gemm_h<false, true>,
                             cudaFuncAttributeMaxDynamicSharedMemorySize, GEMM_SMEM_H);
        cudaFuncSetAttribute((const void*)gemm_h<true, false>,
                             cudaFuncAttributeMaxDynamicSharedMemorySize, GEMM_SMEM_H);
        cudaStreamCreateWithFlags(&s1, cudaStreamNonBlocking);
        cudaStreamCreateWithFlags(&s2, cudaStreamNonBlocking);
        cudaEventCreateWithFlags(&evFork,  cudaEventDisableTiming);
        cudaEventCreateWithFlags(&evCsr,   cudaEventDisableTiming);
        cudaEventCreateWithFlags(&evPack,  cudaEventDisableTiming);
        cudaEventCreateWithFlags(&evInitG, cudaEventDisableTiming);
    }

    const int nwb  = (n + 255) / 256;
    const int etb  = (E + 255) / 256;
    const int nblk = (n + 255) / 256;
    const int n8b  = (n * 8 + 255) / 256;
    const int nab  = (n + 3) / 4;               // 4 nodes per block (2 warps/node)
    const int mtiles = (n + 127) / 128;
    dim3 gemm_grid(mtiles, 8);
    dim3 gate_grid(mtiles, 2);

    // ---- fork ----
    cudaEventRecord(evFork, 0);
    cudaStreamWaitEvent(s1, evFork, 0);
    cudaStreamWaitEvent(s2, evFork, 0);

    // s1: CSR build (needed first by node_attn L1)
    hist_zero<<<nwb, 256, 0, s1>>>(n);
    hist<<<etb, 256, 0, s1>>>(dst, E);
    scan_blocks<<<nblk, 256, 0, s1>>>(n);
    scan_tops<<<1, 512, 0, s1>>>(nblk);
    scan_add<<<nblk, 256, 0, s1>>>(n, E);
    fill_csr<<<etb, 256, 0, s1>>>(src, dst, E);
    cudaEventRecord(evCsr, s1);

    // s2: layer-2 + gate weight packs, graph init (independent of main chain)
    pack4<<<(512 * 128 + 255) / 256, 256, 0, s2>>>(wq2, bq2, wk2, bk2, wv2, bv2, ws2, bs2,
                                                   p_Wh2, p_B2);
    pack1<<<(128 * 128 + 255) / 256, 256, 0, s2>>>(gw1, gb1, p_Whg, p_Bg);
    init_graph<<<32, 256, 0, s2>>>();
    cudaEventRecord(evPack, s2);

    // ---- main: Layer 1 ----
    pack4<<<(512 * 128 + 255) / 256, 256>>>(wq1, bq1, wk1, bk1, wv1, bv1, ws1, bs1,
                                            p_Wh1, p_B1);
    gemm_h<false, true><<<gemm_grid, 256, GEMM_SMEM_H>>>(x, n, p_Wh1, p_B1, p_qkvs, 512);
    cudaStreamWaitEvent(0, evCsr, 0);
    node_attn<<<nab, 256>>>(n);

    // ---- Layer 2 ----
    cudaStreamWaitEvent(0, evPack, 0);
    gemm_h<false, true><<<gemm_grid, 256, GEMM_SMEM_H>>>(p_h, n, p_Wh2, p_B2, p_qkvs, 512);
    node_attn<<<nab, 256>>>(n);

    // ---- Global attention ----
    gemm_h<true, false><<<gate_grid, 256, GEMM_SMEM_H>>>(p_h, n, p_Whg, p_Bg, p_gh, 128);
    gate_dot<<<n8b, 256>>>(gw2, gb2, batch, n);
    pool_kernel<<<(n + POOL_CHUNK - 1) / POOL_CHUNK, 128>>>(batch, n);

    // ---- Classifier ----
    classifier<<<1, 1024>>>(cw, cb, out);
}

// round 9
// speedup vs baseline: 1.0644x; 1.0644x over previous
#include <cuda_runtime.h>
#include <cuda_fp16.h>
#include <cstdint>

// Problem constants
#define NN 100000
#define EE 1600000
#define GGR 64

// ---------------- static device scratch ----------------
__device__ float    g_qkvs[(size_t)NN * 512]; // q[0:128) (k/v fp32 slots unused) skip[384:512)
__device__ __half   g_kv16[(size_t)NN * 256]; // per node: k[0:128) v[128:256) fp16
__device__ float    g_h   [(size_t)NN * 128];
__device__ float    g_gh  [(size_t)NN * 128];
__device__ float    g_gate[NN];
__device__ float    g_pool[GGR * 128];
__device__ float    g_gs[GGR];
__device__ __half   g_Wh1[512 * 128];
__device__ __half   g_Wh2[512 * 128];
__device__ __half   g_Whg[128 * 128];
__device__ float    g_B1[512];
__device__ float    g_B2[512];
__device__ float    g_Bg[128];
// CSR (dst-sorted adjacency)
__device__ int      g_off[NN + 1];
__device__ int      g_cur[NN];
__device__ int      g_csrc[EE];
__device__ int      g_bsums[512];

// ---------------- fp16 mma ----------------
__device__ __forceinline__ void mma16(float* d, const uint32_t* a, const uint32_t* b) {
    asm volatile("mma.sync.aligned.m16n8k16.row.col.f32.f16.f16.f32 "
        "{%0,%1,%2,%3}, {%4,%5,%6,%7}, {%8,%9}, {%0,%1,%2,%3};"
        : "+f"(d[0]), "+f"(d[1]), "+f"(d[2]), "+f"(d[3])
        : "r"(a[0]), "r"(a[1]), "r"(a[2]), "r"(a[3]), "r"(b[0]), "r"(b[1]));
}

// ---------------- weight packing (fp16) ----------------
__global__ void pack4(const float* __restrict__ wq, const float* __restrict__ bq,
                      const float* __restrict__ wk, const float* __restrict__ bk,
                      const float* __restrict__ wv, const float* __restrict__ bv,
                      const float* __restrict__ ws, const float* __restrict__ bs,
                      __half* __restrict__ Wh, float* __restrict__ B) {
    int idx = blockIdx.x * blockDim.x + threadIdx.x;
    if (idx < 512 * 128) {
        int orow = idx >> 7, k = idx & 127;
        int sel = orow >> 7, r = orow & 127;
        const float* w = (sel == 0) ? wq : (sel == 1) ? wk : (sel == 2) ? wv : ws;
        Wh[idx] = __float2half_rn(w[r * 128 + k]);
    }
    if (idx < 512) {
        int sel = idx >> 7, r = idx & 127;
        const float* b = (sel == 0) ? bq : (sel == 1) ? bk : (sel == 2) ? bv : bs;
        B[idx] = b[r];
    }
}

__global__ void pack1(const float* __restrict__ w, const float* __restrict__ b,
                      __half* __restrict__ Wh, float* __restrict__ B) {
    int idx = blockIdx.x * blockDim.x + threadIdx.x;
    if (idx < 128 * 128) Wh[idx] = __float2half_rn(w[idx]);
    if (idx < 128) B[idx] = b[idx];
}

// ---------------- fp16 single-pass mma GEMM ----------------
#define KH 136
#define GEMM_SMEM_H ((128 + 64) * KH * 2)        // 52224 B

template<bool RELU, bool WRITEKV>
__global__ __launch_bounds__(256, 2)
void gemm_h(const float* __restrict__ X, int n,
            const __half* __restrict__ Wh, const float* __restrict__ bias,
            float* __restrict__ Y, int OUT) {
    extern __shared__ __half sh[];
    __half* sX = sh;               // [128][KH]
    __half* sW = sh + 128 * KH;    // [64][KH]

    const int tid = threadIdx.x, wid = tid >> 5, lane = tid & 31;
    const int wm = wid & 3, wn = wid >> 2;
    const int row0 = blockIdx.x * 128, col0 = blockIdx.y * 64;
    const int grp = lane >> 2, tg = lane & 3;

#pragma unroll
    for (int j = 0; j < 8; j++) {
        int idx = tid + 256 * j;
        int r = idx >> 4, c8 = idx & 15;
        int gr = row0 + r;
        float4 v0 = make_float4(0.f, 0.f, 0.f, 0.f);
        float4 v1 = make_float4(0.f, 0.f, 0.f, 0.f);
        if (gr < n) {
            v0 = *(const float4*)(X + (size_t)gr * 128 + c8 * 8);
            v1 = *(const float4*)(X + (size_t)gr * 128 + c8 * 8 + 4);
        }
        __half2 h0 = __floats2half2_rn(v0.x, v0.y);
        __half2 h1 = __floats2half2_rn(v0.z, v0.w);
        __half2 h2 = __floats2half2_rn(v1.x, v1.y);
        __half2 h3 = __floats2half2_rn(v1.z, v1.w);
        uint4 pk;
        pk.x = *(uint32_t*)&h0; pk.y = *(uint32_t*)&h1;
        pk.z = *(uint32_t*)&h2; pk.w = *(uint32_t*)&h3;
        *(uint4*)(sX + r * KH + c8 * 8) = pk;
    }
#pragma unroll
    for (int j = 0; j < 4; j++) {
        int idx = tid + 256 * j;
        int r = idx >> 4, c8 = idx & 15;
        *(uint4*)(sW + r * KH + c8 * 8) =
            *(const uint4*)(Wh + (size_t)(col0 + r) * 128 + c8 * 8);
    }
    __syncthreads();

    float acc[2][4][4];
#pragma unroll
    for (int mt = 0; mt < 2; mt++)
#pragma unroll
        for (int nt = 0; nt < 4; nt++)
#pragma unroll
            for (int q = 0; q < 4; q++) acc[mt][nt][q] = 0.f;

#pragma unroll
    for (int ks = 0; ks < 8; ks++) {
        const int c = ks * 16 + 2 * tg;
        uint32_t a[2][4];
#pragma unroll
        for (int mt = 0; mt < 2; mt++) {
            const int r = wm * 32 + mt * 16 + grp;
            a[mt][0] = *(const uint32_t*)(sX + r * KH + c);
            a[mt][1] = *(const uint32_t*)(sX + (r + 8) * KH + c);
            a[mt][2] = *(const uint32_t*)(sX + r * KH + c + 8);
            a[mt][3] = *(const uint32_t*)(sX + (r + 8) * KH + c + 8);
        }
        uint32_t b[4][2];
#pragma unroll
        for (int nt = 0; nt < 4; nt++) {
            const int nr = wn * 32 + nt * 8 + grp;
            b[nt][0] = *(const uint32_t*)(sW + nr * KH + c);
            b[nt][1] = *(const uint32_t*)(sW + nr * KH + c + 8);
        }
#pragma unroll
        for (int mt = 0; mt < 2; mt++)
#pragma unroll
            for (int nt = 0; nt < 4; nt++) mma16(acc[mt][nt], a[mt], b[nt]);
    }

#pragma unroll
    for (int mt = 0; mt < 2; mt++) {
        const int gr = row0 + wm * 32 + mt * 16 + grp;
#pragma unroll
        for (int nt = 0; nt < 4; nt++) {
            const int col = col0 + wn * 32 + nt * 8 + 2 * tg;
            const float b0 = bias[col], b1 = bias[col + 1];
            float2 o1 = make_float2(acc[mt][nt][0] + b0, acc[mt][nt][1] + b1);
            float2 o2 = make_float2(acc[mt][nt][2] + b0, acc[mt][nt][3] + b1);
            if (RELU) {
                o1.x = fmaxf(o1.x, 0.f); o1.y = fmaxf(o1.y, 0.f);
                o2.x = fmaxf(o2.x, 0.f); o2.y = fmaxf(o2.y, 0.f);
            }
            const bool mid = WRITEKV && (col >= 128 && col < 384);
            if (!mid) {
                if (gr < n)     *(float2*)(Y + (size_t)gr * OUT + col) = o1;
                if (gr + 8 < n) *(float2*)(Y + (size_t)(gr + 8) * OUT + col) = o2;
            } else {
                if (gr < n)
                    *(__half2*)(g_kv16 + (size_t)gr * 256 + (col - 128)) =
                        __floats2half2_rn(o1.x, o1.y);
                if (gr + 8 < n)
                    *(__half2*)(g_kv16 + (size_t)(gr + 8) * 256 + (col - 128)) =
                        __floats2half2_rn(o2.x, o2.y);
            }
        }
    }
}

// ================= CSR build =================
__global__ void hist_zero(int n) {
    int i = blockIdx.x * blockDim.x + threadIdx.x;
    if (i < n) g_cur[i] = 0;
}
__global__ void hist(const int* __restrict__ dst, int E) {
    int e = blockIdx.x * blockDim.x + threadIdx.x;
    if (e < E) atomicAdd(&g_cur[dst[e]], 1);
}
__global__ void scan_blocks(int n) {
    __shared__ int sm[256];
    int t = threadIdx.x;
    int i = blockIdx.x * 256 + t;
    int v = (i < n) ? g_cur[i] : 0;
    sm[t] = v;
    __syncthreads();
#pragma unroll
    for (int o = 1; o < 256; o <<= 1) {
        int x = (t >= o) ? sm[t - o] : 0;
        __syncthreads();
        sm[t] += x;
        __syncthreads();
    }
    if (i < n) g_off[i] = sm[t] - v;
    if (t == 255) g_bsums[blockIdx.x] = sm[255];
}
__global__ void scan_tops(int nblk) {
    __shared__ int sm[512];
    int t = threadIdx.x;
    int v = (t < nblk) ? g_bsums[t] : 0;
    sm[t] = v;
    __syncthreads();
#pragma unroll
    for (int o = 1; o < 512; o <<= 1) {
        int x = (t >= o) ? sm[t - o] : 0;
        __syncthreads();
        sm[t] += x;
        __syncthreads();
    }
    if (t < nblk) g_bsums[t] = sm[t] - v;
}
__global__ void scan_add(int n, int E) {
    int i = blockIdx.x * 256 + threadIdx.x;
    if (i < n) {
        int o = g_off[i] + g_bsums[blockIdx.x];
        g_off[i] = o;
        g_cur[i] = o;
    }
    if (i == 0) g_off[n] = E;
}
__global__ void fill_csr(const int* __restrict__ src, const int* __restrict__ dst, int E) {
    int e = blockIdx.x * blockDim.x + threadIdx.x;
    if (e >= E) return;
    int p = atomicAdd(&g_cur[dst[e]], 1);
    g_csrc[p] = src[e];
}

// ================= fused per-node attention (1 warp/node, 4-edge pipeline) =================
__global__ __launch_bounds__(256, 8)
void node_attn(int n) {
    int node = (blockIdx.x * blockDim.x + threadIdx.x) >> 5;
    int lane = threadIdx.x & 31;
    if (node >= n) return;
    const float scale = 0.08838834764831845f;  // 1/sqrt(128)
    const float* base = g_qkvs + (size_t)node * 512;
    float4 q = *(const float4*)(base + lane * 4);
    q.x *= scale; q.y *= scale; q.z *= scale; q.w *= scale;

    int beg = g_off[node], end = g_off[node + 1];
    float4 acc = make_float4(0.f, 0.f, 0.f, 0.f);
    float sum = 0.f;

    int j = beg;
    for (; j + 4 <= end; j += 4) {
        const __half* r[4];
        float d[4];
#pragma unroll
        for (int u = 0; u < 4; u++) r[u] = g_kv16 + (size_t)g_csrc[j + u] * 256;
#pragma unroll
        for (int u = 0; u < 4; u++) {
            uint2 kk = *(const uint2*)(r[u] + lane * 4);
            float2 a = __half22float2(*(const __half2*)&kk.x);
            float2 b = __half22float2(*(const __half2*)&kk.y);
            d[u] = q.x * a.x + q.y * a.y + q.z * b.x + q.w * b.y;
        }
#pragma unroll
        for (int o = 16; o; o >>= 1) {
#pragma unroll
            for (int u = 0; u < 4; u++) d[u] += __shfl_xor_sync(0xffffffffu, d[u], o);
        }
        float e[4];
#pragma unroll
        for (int u = 0; u < 4; u++) e[u] = __expf(d[u]);
#pragma unroll
        for (int u = 0; u < 4; u++) {
            uint2 vv = *(const uint2*)(r[u] + 128 + lane * 4);
            float2 va = __half22float2(*(const __half2*)&vv.x);
            float2 vb = __half22float2(*(const __half2*)&vv.y);
            acc.x += e[u] * va.x; acc.y += e[u] * va.y;
            acc.z += e[u] * vb.x; acc.w += e[u] * vb.y;
            sum += e[u];
        }
    }
    for (; j < end; j++) {
        const __half* r0 = g_kv16 + (size_t)g_csrc[j] * 256;
        uint2 kk = *(const uint2*)(r0 + lane * 4);
        float2 a = __half22float2(*(const __half2*)&kk.x);
        float2 b = __half22float2(*(const __half2*)&kk.y);
        float d0 = q.x * a.x + q.y * a.y + q.z * b.x + q.w * b.y;
#pragma unroll
        for (int o = 16; o; o >>= 1) d0 += __shfl_xor_sync(0xffffffffu, d0, o);
        float e0 = __expf(d0);
        uint2 vv = *(const uint2*)(r0 + 128 + lane * 4);
        float2 va = __half22float2(*(const __half2*)&vv.x);
        float2 vb = __half22float2(*(const __half2*)&vv.y);
        acc.x += e0 * va.x; acc.y += e0 * va.y;
        acc.z += e0 * vb.x; acc.w += e0 * vb.y;
        sum += e0;
    }

    float inv = (end > beg) ? (1.f / sum) : 0.f;
    float4 skip = *(const float4*)(base + 384 + lane * 4);
    float4 o;
    o.x = fmaxf(acc.x * inv + skip.x, 0.f);
    o.y = fmaxf(acc.y * inv + skip.y, 0.f);
    o.z = fmaxf(acc.z * inv + skip.z, 0.f);
    o.w = fmaxf(acc.w * inv + skip.w, 0.f);
    *(float4*)(g_h + (size_t)node * 128 + lane * 4) = o;
}

// ---------------- graph-level ----------------
__global__ void init_graph() {
    int i = blockIdx.x * blockDim.x + threadIdx.x;
    if (i < GGR * 128) g_pool[i] = 0.f;
    if (i < GGR) g_gs[i] = 0.f;
}

__global__ void gate_dot(const float* __restrict__ gw2, const float* __restrict__ gb2,
                         const int* __restrict__ batch, int n) {
    int w = (blockIdx.x * blockDim.x + threadIdx.x) >> 3;
    int t = threadIdx.x & 7;
    if (w >= n) return;
    const float* hp = g_gh + (size_t)w * 128;
    float dot = 0.f;
#pragma unroll
    for (int i = 0; i < 4; i++) {
        float4 a = *(const float4*)(hp + (t + 8 * i) * 4);
        float4 b = *(const float4*)(gw2 + (t + 8 * i) * 4);
        dot += a.x * b.x + a.y * b.y + a.z * b.z + a.w * b.w;
    }
#pragma unroll
    for (int o = 4; o; o >>= 1) dot += __shfl_xor_sync(0xffffffffu, dot, o);
    if (t == 0) {
        float ev = __expf(dot + gb2[0]);
        g_gate[w] = ev;
        atomicAdd(&g_gs[batch[w]], ev);
    }
}

#define POOL_CHUNK 512
__global__ void pool_kernel(const int* __restrict__ batch, int n) {
    int d = threadIdx.x;
    int n0 = blockIdx.x * POOL_CHUNK;
    int n1 = min(n0 + POOL_CHUNK, n);
    if (n0 >= n) return;
    int curb = batch[n0];
    float acc = 0.f;
    for (int node = n0; node < n1; node++) {
        int b = batch[node];
        if (b != curb) {
            atomicAdd(&g_pool[curb * 128 + d], acc);
            acc = 0.f; curb = b;
        }
        float wgt = g_gate[node] / g_gs[b];
        acc += wgt * g_h[(size_t)node * 128 + d];
    }
    atomicAdd(&g_pool[curb * 128 + d], acc);
}

__global__ void classifier(const float* __restrict__ cw, const float* __restrict__ cb,
                           float* __restrict__ out) {
    int i = threadIdx.x;
    if (i >= GGR * 10) return;
    int g = i / 10, c = i % 10;
    float a = cb[c];
#pragma unroll 16
    for (int k = 0; k < 128; k++) a += g_pool[g * 128 + k] * cw[c * 128 + k];
    out[i] = a;
}

// ---------------- host orchestration ----------------
extern "C" void kernel_launch(void* const* d_in, const int* in_sizes, int n_in,
                              void* d_out, int out_size) {
    const float* x   = (const float*)d_in[0];
    const int* eidx  = (const int*)d_in[1];
    const int* batch = (const int*)d_in[2];
    const float *wq1 = (const float*)d_in[3],  *bq1 = (const float*)d_in[4];
    const float *wk1 = (const float*)d_in[5],  *bk1 = (const float*)d_in[6];
    const float *wv1 = (const float*)d_in[7],  *bv1 = (const float*)d_in[8];
    const float *ws1 = (const float*)d_in[9],  *bs1 = (const float*)d_in[10];
    const float *wq2 = (const float*)d_in[11], *bq2 = (const float*)d_in[12];
    const float *wk2 = (const float*)d_in[13], *bk2 = (const float*)d_in[14];
    const float *wv2 = (const float*)d_in[15], *bv2 = (const float*)d_in[16];
    const float *ws2 = (const float*)d_in[17], *bs2 = (const float*)d_in[18];
    const float *gw1 = (const float*)d_in[19], *gb1 = (const float*)d_in[20];
    const float *gw2 = (const float*)d_in[21], *gb2 = (const float*)d_in[22];
    const float *cw  = (const float*)d_in[23], *cb  = (const float*)d_in[24];
    float* out = (float*)d_out;

    const int n = in_sizes[0] / 128;
    const int E = in_sizes[1] / 2;
    const int* src = eidx;
    const int* dst = eidx + E;

    static float* p_qkvs = nullptr; static float* p_h = nullptr; static float* p_gh = nullptr;
    static __half *p_Wh1 = nullptr, *p_Wh2 = nullptr, *p_Whg = nullptr;
    static float  *p_B1 = nullptr,  *p_B2 = nullptr,  *p_Bg = nullptr;
    if (!p_qkvs) {
        cudaGetSymbolAddress((void**)&p_qkvs, g_qkvs);
        cudaGetSymbolAddress((void**)&p_h,    g_h);
        cudaGetSymbolAddress((void**)&p_gh,   g_gh);
        cudaGetSymbolAddress((void**)&p_Wh1,  g_Wh1);
        cudaGetSymbolAddress((void**)&p_Wh2,  g_Wh2);
        cudaGetSymbolAddress((void**)&p_Whg,  g_Whg);
        cudaGetSymbolAddress((void**)&p_B1,   g_B1);
        cudaGetSymbolAddress((void**)&p_B2,   g_B2);
        cudaGetSymbolAddress((void**)&p_Bg,   g_Bg);
        cudaFuncSetAttribute((const void*)gemm_h<false, true>,
                             cudaFuncAttributeMaxDynamicSharedMemorySize, GEMM_SMEM_H);
        cudaFuncSetAttribute((const void*)gemm_h<true, false>,
                             cudaFuncAttributeMaxDynamicSharedMemorySize, GEMM_SMEM_H);
    }

    const int nwb  = (n + 255) / 256;
    const int etb  = (E + 255) / 256;
    const int nblk = (n + 255) / 256;
    const int n8b  = (n * 8 + 255) / 256;
    const int nab  = (n * 32 + 255) / 256;      // 1 warp/node
    const int mtiles = (n + 127) / 128;
    dim3 gemm_grid(mtiles, 8);
    dim3 gate_grid(mtiles, 2);

    // ---- all weight packs up front (tiny; no downstream stalls) ----
    pack4<<<(512 * 128 + 255) / 256, 256>>>(wq1, bq1, wk1, bk1, wv1, bv1, ws1, bs1,
                                            p_Wh1, p_B1);
    pack4<<<(512 * 128 + 255) / 256, 256>>>(wq2, bq2, wk2, bk2, wv2, bv2, ws2, bs2,
                                            p_Wh2, p_B2);
    pack1<<<(128 * 128 + 255) / 256, 256>>>(gw1, gb1, p_Whg, p_Bg);
    init_graph<<<32, 256>>>();

    // ---- CSR build ----
    hist_zero<<<nwb, 256>>>(n);
    hist<<<etb, 256>>>(dst, E);
    scan_blocks<<<nblk, 256>>>(n);
    scan_tops<<<1, 512>>>(nblk);
    scan_add<<<nblk, 256>>>(n, E);
    fill_csr<<<etb, 256>>>(src, dst, E);

    // ---- Layer 1 ----
    gemm_h<false, true><<<gemm_grid, 256, GEMM_SMEM_H>>>(x, n, p_Wh1, p_B1, p_qkvs, 512);
    node_attn<<<nab, 256>>>(n);

    // ---- Layer 2 ----
    gemm_h<false, true><<<gemm_grid, 256, GEMM_SMEM_H>>>(p_h, n, p_Wh2, p_B2, p_qkvs, 512);
    node_attn<<<nab, 256>>>(n);

    // ---- Global attention ----
    gemm_h<true, false><<<gate_grid, 256, GEMM_SMEM_H>>>(p_h, n, p_Whg, p_Bg, p_gh, 128);
    gate_dot<<<n8b, 256>>>(gw2, gb2, batch, n);
    pool_kernel<<<(n + POOL_CHUNK - 1) / POOL_CHUNK, 128>>>(batch, n);

    // ---- Classifier ----
    classifier<<<1, 1024>>>(cw, cb, out);
}

// round 10
// speedup vs baseline: 1.2890x; 1.2110x over previous
#include <cuda_runtime.h>
#include <cuda_fp16.h>
#include <cstdint>

// Problem constants
#define NN 100000
#define EE 1600000
#define GGR 64

// ---------------- static device scratch ----------------
__device__ float    g_qkvs[(size_t)NN * 512]; // q[0:128) (k/v fp32 slots unused) skip[384:512)
__device__ __half   g_kv16[(size_t)NN * 256]; // per node: k[0:128) v[128:256) fp16
__device__ float    g_h   [(size_t)NN * 128];
__device__ float    g_gate[NN];               // raw gate logit accum -> exp value
__device__ float    g_pool[GGR * 128];
__device__ float    g_gs[GGR];
__device__ __half   g_Wh1[512 * 128];
__device__ __half   g_Wh2[512 * 128];
__device__ __half   g_Whg[128 * 128];
__device__ float    g_B1[512];
__device__ float    g_B2[512];
__device__ float    g_Bg[128];
// CSR (dst-sorted adjacency)
__device__ int      g_off[NN + 1];
__device__ int      g_cur[NN];
__device__ int      g_csrc[EE];
__device__ int      g_bsums[512];

// ---------------- fp16 mma ----------------
__device__ __forceinline__ void mma16(float* d, const uint32_t* a, const uint32_t* b) {
    asm volatile("mma.sync.aligned.m16n8k16.row.col.f32.f16.f16.f32 "
        "{%0,%1,%2,%3}, {%4,%5,%6,%7}, {%8,%9}, {%0,%1,%2,%3};"
        : "+f"(d[0]), "+f"(d[1]), "+f"(d[2]), "+f"(d[3])
        : "r"(a[0]), "r"(a[1]), "r"(a[2]), "r"(a[3]), "r"(b[0]), "r"(b[1]));
}

// ---------------- weight packing (fp16) ----------------
__global__ void pack4(const float* __restrict__ wq, const float* __restrict__ bq,
                      const float* __restrict__ wk, const float* __restrict__ bk,
                      const float* __restrict__ wv, const float* __restrict__ bv,
                      const float* __restrict__ ws, const float* __restrict__ bs,
                      __half* __restrict__ Wh, float* __restrict__ B) {
    int idx = blockIdx.x * blockDim.x + threadIdx.x;
    if (idx < 512 * 128) {
        int orow = idx >> 7, k = idx & 127;
        int sel = orow >> 7, r = orow & 127;
        const float* w = (sel == 0) ? wq : (sel == 1) ? wk : (sel == 2) ? wv : ws;
        Wh[idx] = __float2half_rn(w[r * 128 + k]);
    }
    if (idx < 512) {
        int sel = idx >> 7, r = idx & 127;
        const float* b = (sel == 0) ? bq : (sel == 1) ? bk : (sel == 2) ? bv : bs;
        B[idx] = b[r];
    }
}

__global__ void pack1(const float* __restrict__ w, const float* __restrict__ b,
                      __half* __restrict__ Wh, float* __restrict__ B) {
    int idx = blockIdx.x * blockDim.x + threadIdx.x;
    if (idx < 128 * 128) Wh[idx] = __float2half_rn(w[idx]);
    if (idx < 128) B[idx] = b[idx];
}

// ---------------- fp16 single-pass mma GEMM ----------------
// GATEDOT variant: no Y stores; instead accumulate per-row dot with gw2 into g_gate.
#define KH 136
#define GEMM_SMEM_H ((128 + 64) * KH * 2)        // 52224 B

template<bool RELU, bool WRITEKV, bool GATEDOT>
__global__ __launch_bounds__(256, 2)
void gemm_h(const float* __restrict__ X, int n,
            const __half* __restrict__ Wh, const float* __restrict__ bias,
            float* __restrict__ Y, int OUT, const float* __restrict__ gw2d) {
    extern __shared__ __half sh[];
    __half* sX = sh;               // [128][KH]
    __half* sW = sh + 128 * KH;    // [64][KH]

    const int tid = threadIdx.x, wid = tid >> 5, lane = tid & 31;
    const int wm = wid & 3, wn = wid >> 2;
    const int row0 = blockIdx.x * 128, col0 = blockIdx.y * 64;
    const int grp = lane >> 2, tg = lane & 3;

#pragma unroll
    for (int j = 0; j < 8; j++) {
        int idx = tid + 256 * j;
        int r = idx >> 4, c8 = idx & 15;
        int gr = row0 + r;
        float4 v0 = make_float4(0.f, 0.f, 0.f, 0.f);
        float4 v1 = make_float4(0.f, 0.f, 0.f, 0.f);
        if (gr < n) {
            v0 = *(const float4*)(X + (size_t)gr * 128 + c8 * 8);
            v1 = *(const float4*)(X + (size_t)gr * 128 + c8 * 8 + 4);
        }
        __half2 h0 = __floats2half2_rn(v0.x, v0.y);
        __half2 h1 = __floats2half2_rn(v0.z, v0.w);
        __half2 h2 = __floats2half2_rn(v1.x, v1.y);
        __half2 h3 = __floats2half2_rn(v1.z, v1.w);
        uint4 pk;
        pk.x = *(uint32_t*)&h0; pk.y = *(uint32_t*)&h1;
        pk.z = *(uint32_t*)&h2; pk.w = *(uint32_t*)&h3;
        *(uint4*)(sX + r * KH + c8 * 8) = pk;
    }
#pragma unroll
    for (int j = 0; j < 4; j++) {
        int idx = tid + 256 * j;
        int r = idx >> 4, c8 = idx & 15;
        *(uint4*)(sW + r * KH + c8 * 8) =
            *(const uint4*)(Wh + (size_t)(col0 + r) * 128 + c8 * 8);
    }
    __syncthreads();

    float acc[2][4][4];
#pragma unroll
    for (int mt = 0; mt < 2; mt++)
#pragma unroll
        for (int nt = 0; nt < 4; nt++)
#pragma unroll
            for (int q = 0; q < 4; q++) acc[mt][nt][q] = 0.f;

#pragma unroll
    for (int ks = 0; ks < 8; ks++) {
        const int c = ks * 16 + 2 * tg;
        uint32_t a[2][4];
#pragma unroll
        for (int mt = 0; mt < 2; mt++) {
            const int r = wm * 32 + mt * 16 + grp;
            a[mt][0] = *(const uint32_t*)(sX + r * KH + c);
            a[mt][1] = *(const uint32_t*)(sX + (r + 8) * KH + c);
            a[mt][2] = *(const uint32_t*)(sX + r * KH + c + 8);
            a[mt][3] = *(const uint32_t*)(sX + (r + 8) * KH + c + 8);
        }
        uint32_t b[4][2];
#pragma unroll
        for (int nt = 0; nt < 4; nt++) {
            const int nr = wn * 32 + nt * 8 + grp;
            b[nt][0] = *(const uint32_t*)(sW + nr * KH + c);
            b[nt][1] = *(const uint32_t*)(sW + nr * KH + c + 8);
        }
#pragma unroll
        for (int mt = 0; mt < 2; mt++)
#pragma unroll
            for (int nt = 0; nt < 4; nt++) mma16(acc[mt][nt], a[mt], b[nt]);
    }

    float rp[2][2] = {{0.f, 0.f}, {0.f, 0.f}};   // [mt][row-half] gate partials

#pragma unroll
    for (int mt = 0; mt < 2; mt++) {
        const int gr = row0 + wm * 32 + mt * 16 + grp;
#pragma unroll
        for (int nt = 0; nt < 4; nt++) {
            const int col = col0 + wn * 32 + nt * 8 + 2 * tg;
            const float b0 = bias[col], b1 = bias[col + 1];
            float2 o1 = make_float2(acc[mt][nt][0] + b0, acc[mt][nt][1] + b1);
            float2 o2 = make_float2(acc[mt][nt][2] + b0, acc[mt][nt][3] + b1);
            if (RELU) {
                o1.x = fmaxf(o1.x, 0.f); o1.y = fmaxf(o1.y, 0.f);
                o2.x = fmaxf(o2.x, 0.f); o2.y = fmaxf(o2.y, 0.f);
            }
            if (GATEDOT) {
                const float w0 = gw2d[col], w1 = gw2d[col + 1];
                rp[mt][0] += o1.x * w0 + o1.y * w1;
                rp[mt][1] += o2.x * w0 + o2.y * w1;
            } else {
                const bool mid = WRITEKV && (col >= 128 && col < 384);
                if (!mid) {
                    if (gr < n)     *(float2*)(Y + (size_t)gr * OUT + col) = o1;
                    if (gr + 8 < n) *(float2*)(Y + (size_t)(gr + 8) * OUT + col) = o2;
                } else {
                    if (gr < n)
                        *(__half2*)(g_kv16 + (size_t)gr * 256 + (col - 128)) =
                            __floats2half2_rn(o1.x, o1.y);
                    if (gr + 8 < n)
                        *(__half2*)(g_kv16 + (size_t)(gr + 8) * 256 + (col - 128)) =
                            __floats2half2_rn(o2.x, o2.y);
                }
            }
        }
    }

    if (GATEDOT) {
        // reduce partials across the 4 tg lanes, one atomic per row per warp
#pragma unroll
        for (int mt = 0; mt < 2; mt++)
#pragma unroll
            for (int h = 0; h < 2; h++) {
                float v = rp[mt][h];
                v += __shfl_xor_sync(0xffffffffu, v, 1);
                v += __shfl_xor_sync(0xffffffffu, v, 2);
                if (tg == 0) {
                    const int row = row0 + wm * 32 + mt * 16 + grp + h * 8;
                    if (row < n) atomicAdd(&g_gate[row], v);
                }
            }
    }
}

// ================= CSR build =================
__global__ void hist_zero(int n) {
    int i = blockIdx.x * blockDim.x + threadIdx.x;
    if (i < n) { g_cur[i] = 0; g_gate[i] = 0.f; }
}
__global__ void hist(const int* __restrict__ dst, int E) {
    int e = blockIdx.x * blockDim.x + threadIdx.x;
    if (e < E) atomicAdd(&g_cur[dst[e]], 1);
}
__global__ void scan_blocks(int n) {
    __shared__ int sm[256];
    int t = threadIdx.x;
    int i = blockIdx.x * 256 + t;
    int v = (i < n) ? g_cur[i] : 0;
    sm[t] = v;
    __syncthreads();
#pragma unroll
    for (int o = 1; o < 256; o <<= 1) {
        int x = (t >= o) ? sm[t - o] : 0;
        __syncthreads();
        sm[t] += x;
        __syncthreads();
    }
    if (i < n) g_off[i] = sm[t] - v;
    if (t == 255) g_bsums[blockIdx.x] = sm[255];
}
__global__ void scan_tops(int nblk) {
    __shared__ int sm[512];
    int t = threadIdx.x;
    int v = (t < nblk) ? g_bsums[t] : 0;
    sm[t] = v;
    __syncthreads();
#pragma unroll
    for (int o = 1; o < 512; o <<= 1) {
        int x = (t >= o) ? sm[t - o] : 0;
        __syncthreads();
        sm[t] += x;
        __syncthreads();
    }
    if (t < nblk) g_bsums[t] = sm[t] - v;
}
__global__ void scan_add(int n, int E) {
    int i = blockIdx.x * 256 + threadIdx.x;
    if (i < n) {
        int o = g_off[i] + g_bsums[blockIdx.x];
        g_off[i] = o;
        g_cur[i] = o;
    }
    if (i == 0) g_off[n] = E;
}
__global__ void fill_csr(const int* __restrict__ src, const int* __restrict__ dst, int E) {
    int e = blockIdx.x * blockDim.x + threadIdx.x;
    if (e >= E) return;
    int p = atomicAdd(&g_cur[dst[e]], 1);
    g_csrc[p] = src[e];
}

// ================= fused per-node attention (prefetch 8 loads, 4-edge pipeline) =================
__global__ __launch_bounds__(256, 6)
void node_attn(int n) {
    int node = (blockIdx.x * blockDim.x + threadIdx.x) >> 5;
    int lane = threadIdx.x & 31;
    if (node >= n) return;
    const float scale = 0.08838834764831845f;  // 1/sqrt(128)
    const float* base = g_qkvs + (size_t)node * 512;
    float4 q = *(const float4*)(base + lane * 4);
    q.x *= scale; q.y *= scale; q.z *= scale; q.w *= scale;

    int beg = g_off[node], end = g_off[node + 1];
    float4 acc = make_float4(0.f, 0.f, 0.f, 0.f);
    float sum = 0.f;

    int j = beg;
    for (; j + 4 <= end; j += 4) {
        const __half* r[4];
#pragma unroll
        for (int u = 0; u < 4; u++) r[u] = g_kv16 + (size_t)g_csrc[j + u] * 256;
        // issue all 8 gathers before any dependent math
        uint2 kk[4], vv[4];
#pragma unroll
        for (int u = 0; u < 4; u++) kk[u] = *(const uint2*)(r[u] + lane * 4);
#pragma unroll
        for (int u = 0; u < 4; u++) vv[u] = *(const uint2*)(r[u] + 128 + lane * 4);

        float d[4];
#pragma unroll
        for (int u = 0; u < 4; u++) {
            float2 a = __half22float2(*(const __half2*)&kk[u].x);
            float2 b = __half22float2(*(const __half2*)&kk[u].y);
            d[u] = q.x * a.x + q.y * a.y + q.z * b.x + q.w * b.y;
        }
#pragma unroll
        for (int o = 16; o; o >>= 1) {
#pragma unroll
            for (int u = 0; u < 4; u++) d[u] += __shfl_xor_sync(0xffffffffu, d[u], o);
        }
#pragma unroll
        for (int u = 0; u < 4; u++) {
            float e = __expf(d[u]);
            float2 va = __half22float2(*(const __half2*)&vv[u].x);
            float2 vb = __half22float2(*(const __half2*)&vv[u].y);
            acc.x += e * va.x; acc.y += e * va.y;
            acc.z += e * vb.x; acc.w += e * vb.y;
            sum += e;
        }
    }
    for (; j < end; j++) {
        const __half* r0 = g_kv16 + (size_t)g_csrc[j] * 256;
        uint2 kk = *(const uint2*)(r0 + lane * 4);
        uint2 vv = *(const uint2*)(r0 + 128 + lane * 4);
        float2 a = __half22float2(*(const __half2*)&kk.x);
        float2 b = __half22float2(*(const __half2*)&kk.y);
        float d0 = q.x * a.x + q.y * a.y + q.z * b.x + q.w * b.y;
#pragma unroll
        for (int o = 16; o; o >>= 1) d0 += __shfl_xor_sync(0xffffffffu, d0, o);
        float e0 = __expf(d0);
        float2 va = __half22float2(*(const __half2*)&vv.x);
        float2 vb = __half22float2(*(const __half2*)&vv.y);
        acc.x += e0 * va.x; acc.y += e0 * va.y;
        acc.z += e0 * vb.x; acc.w += e0 * vb.y;
        sum += e0;
    }

    float inv = (end > beg) ? (1.f / sum) : 0.f;
    float4 skip = *(const float4*)(base + 384 + lane * 4);
    float4 o;
    o.x = fmaxf(acc.x * inv + skip.x, 0.f);
    o.y = fmaxf(acc.y * inv + skip.y, 0.f);
    o.z = fmaxf(acc.z * inv + skip.z, 0.f);
    o.w = fmaxf(acc.w * inv + skip.w, 0.f);
    *(float4*)(g_h + (size_t)node * 128 + lane * 4) = o;
}

// ---------------- graph-level ----------------
__global__ void init_graph() {
    int i = blockIdx.x * blockDim.x + threadIdx.x;
    if (i < GGR * 128) g_pool[i] = 0.f;
    if (i < GGR) g_gs[i] = 0.f;
}

// exp(raw gate + gb2) and per-graph sums
__global__ void node_exp(const float* __restrict__ gb2, const int* __restrict__ batch, int n) {
    int i = blockIdx.x * blockDim.x + threadIdx.x;
    if (i >= n) return;
    float ev = __expf(g_gate[i] + gb2[0]);
    g_gate[i] = ev;
    atomicAdd(&g_gs[batch[i]], ev);
}

#define POOL_CHUNK 512
__global__ void pool_kernel(const int* __restrict__ batch, int n) {
    int d = threadIdx.x;
    int n0 = blockIdx.x * POOL_CHUNK;
    int n1 = min(n0 + POOL_CHUNK, n);
    if (n0 >= n) return;
    int curb = batch[n0];
    float acc = 0.f;
    for (int node = n0; node < n1; node++) {
        int b = batch[node];
        if (b != curb) {
            atomicAdd(&g_pool[curb * 128 + d], acc);
            acc = 0.f; curb = b;
        }
        float wgt = g_gate[node] / g_gs[b];
        acc += wgt * g_h[(size_t)node * 128 + d];
    }
    atomicAdd(&g_pool[curb * 128 + d], acc);
}

__global__ void classifier(const float* __restrict__ cw, const float* __restrict__ cb,
                           float* __restrict__ out) {
    int i = threadIdx.x;
    if (i >= GGR * 10) return;
    int g = i / 10, c = i % 10;
    float a = cb[c];
#pragma unroll 16
    for (int k = 0; k < 128; k++) a += g_pool[g * 128 + k] * cw[c * 128 + k];
    out[i] = a;
}

// ---------------- host orchestration ----------------
extern "C" void kernel_launch(void* const* d_in, const int* in_sizes, int n_in,
                              void* d_out, int out_size) {
    const float* x   = (const float*)d_in[0];
    const int* eidx  = (const int*)d_in[1];
    const int* batch = (const int*)d_in[2];
    const float *wq1 = (const float*)d_in[3],  *bq1 = (const float*)d_in[4];
    const float *wk1 = (const float*)d_in[5],  *bk1 = (const float*)d_in[6];
    const float *wv1 = (const float*)d_in[7],  *bv1 = (const float*)d_in[8];
    const float *ws1 = (const float*)d_in[9],  *bs1 = (const float*)d_in[10];
    const float *wq2 = (const float*)d_in[11], *bq2 = (const float*)d_in[12];
    const float *wk2 = (const float*)d_in[13], *bk2 = (const float*)d_in[14];
    const float *wv2 = (const float*)d_in[15], *bv2 = (const float*)d_in[16];
    const float *ws2 = (const float*)d_in[17], *bs2 = (const float*)d_in[18];
    const float *gw1 = (const float*)d_in[19], *gb1 = (const float*)d_in[20];
    const float *gw2 = (const float*)d_in[21], *gb2 = (const float*)d_in[22];
    const float *cw  = (const float*)d_in[23], *cb  = (const float*)d_in[24];
    float* out = (float*)d_out;

    const int n = in_sizes[0] / 128;
    const int E = in_sizes[1] / 2;
    const int* src = eidx;
    const int* dst = eidx + E;

    static float* p_qkvs = nullptr; static float* p_h = nullptr;
    static __half *p_Wh1 = nullptr, *p_Wh2 = nullptr, *p_Whg = nullptr;
    static float  *p_B1 = nullptr,  *p_B2 = nullptr,  *p_Bg = nullptr;
    if (!p_qkvs) {
        cudaGetSymbolAddress((void**)&p_qkvs, g_qkvs);
        cudaGetSymbolAddress((void**)&p_h,    g_h);
        cudaGetSymbolAddress((void**)&p_Wh1,  g_Wh1);
        cudaGetSymbolAddress((void**)&p_Wh2,  g_Wh2);
        cudaGetSymbolAddress((void**)&p_Whg,  g_Whg);
        cudaGetSymbolAddress((void**)&p_B1,   g_B1);
        cudaGetSymbolAddress((void**)&p_B2,   g_B2);
        cudaGetSymbolAddress((void**)&p_Bg,   g_Bg);
        cudaFuncSetAttribute((const void*)gemm_h<false, true, false>,
                             cudaFuncAttributeMaxDynamicSharedMemorySize, GEMM_SMEM_H);
        cudaFuncSetAttribute((const void*)gemm_h<true, false, true>,
                             cudaFuncAttributeMaxDynamicSharedMemorySize, GEMM_SMEM_H);
    }

    const int nwb  = (n + 255) / 256;
    const int etb  = (E + 255) / 256;
    const int nblk = (n + 255) / 256;
    const int nab  = (n * 32 + 255) / 256;      // 1 warp/node
    const int mtiles = (n + 127) / 128;
    dim3 gemm_grid(mtiles, 8);
    dim3 gate_grid(mtiles, 2);

    // ---- weight packs + graph init up front ----
    pack4<<<(512 * 128 + 255) / 256, 256>>>(wq1, bq1, wk1, bk1, wv1, bv1, ws1, bs1,
                                            p_Wh1, p_B1);
    pack4<<<(512 * 128 + 255) / 256, 256>>>(wq2, bq2, wk2, bk2, wv2, bv2, ws2, bs2,
                                            p_Wh2, p_B2);
    pack1<<<(128 * 128 + 255) / 256, 256>>>(gw1, gb1, p_Whg, p_Bg);
    init_graph<<<32, 256>>>();

    // ---- CSR build (also zeroes g_gate) ----
    hist_zero<<<nwb, 256>>>(n);
    hist<<<etb, 256>>>(dst, E);
    scan_blocks<<<nblk, 256>>>(n);
    scan_tops<<<1, 512>>>(nblk);
    scan_add<<<nblk, 256>>>(n, E);
    fill_csr<<<etb, 256>>>(src, dst, E);

    // ---- Layer 1 ----
    gemm_h<false, true, false><<<gemm_grid, 256, GEMM_SMEM_H>>>(x, n, p_Wh1, p_B1,
                                                                p_qkvs, 512, nullptr);
    node_attn<<<nab, 256>>>(n);

    // ---- Layer 2 ----
    gemm_h<false, true, false><<<gemm_grid, 256, GEMM_SMEM_H>>>(p_h, n, p_Wh2, p_B2,
                                                                p_qkvs, 512, nullptr);
    node_attn<<<nab, 256>>>(n);

    // ---- Global attention (fused gate dot in GEMM epilogue) ----
    gemm_h<true, false, true><<<gate_grid, 256, GEMM_SMEM_H>>>(p_h, n, p_Whg, p_Bg,
                                                               nullptr, 128, gw2);
    node_exp<<<nwb, 256>>>(gb2, batch, n);
    pool_kernel<<<(n + POOL_CHUNK - 1) / POOL_CHUNK, 128>>>(batch, n);

    // ---- Classifier ----
    classifier<<<1, 1024>>>(cw, cb, out);
}

// round 11
// speedup vs baseline: 1.3724x; 1.0647x over previous
#include <cuda_runtime.h>
#include <cuda_fp16.h>
#include <cstdint>

// Problem constants
#define NN 100000
#define EE 1600000
#define GGR 64

// ---------------- static device scratch ----------------
__device__ float    g_qkvs[(size_t)NN * 512]; // q[0:128) (k/v fp32 slots unused) skip[384:512)
__device__ __half   g_kv16[(size_t)NN * 256]; // per node: k[0:128) v[128:256) fp16
__device__ float    g_h   [(size_t)NN * 128];
__device__ float    g_gate[NN];               // raw gate logit accum -> exp value
__device__ float    g_pool[GGR * 128];
__device__ float    g_gs[GGR];
__device__ __half   g_Wh1[512 * 128];
__device__ __half   g_Wh2[512 * 128];
__device__ __half   g_Whg[128 * 128];
__device__ float    g_B1[512];
__device__ float    g_B2[512];
__device__ float    g_Bg[128];
// CSR (dst-sorted adjacency)
__device__ int      g_off[NN + 1];
__device__ int      g_cur[NN];
__device__ int      g_csrc[EE];
__device__ int      g_bsums[512];

// ---------------- fp16 mma ----------------
__device__ __forceinline__ void mma16(float* d, const uint32_t* a, const uint32_t* b) {
    asm volatile("mma.sync.aligned.m16n8k16.row.col.f32.f16.f16.f32 "
        "{%0,%1,%2,%3}, {%4,%5,%6,%7}, {%8,%9}, {%0,%1,%2,%3};"
        : "+f"(d[0]), "+f"(d[1]), "+f"(d[2]), "+f"(d[3])
        : "r"(a[0]), "r"(a[1]), "r"(a[2]), "r"(a[3]), "r"(b[0]), "r"(b[1]));
}

// ---------------- weight packing (fp16) ----------------
__global__ void pack4(const float* __restrict__ wq, const float* __restrict__ bq,
                      const float* __restrict__ wk, const float* __restrict__ bk,
                      const float* __restrict__ wv, const float* __restrict__ bv,
                      const float* __restrict__ ws, const float* __restrict__ bs,
                      __half* __restrict__ Wh, float* __restrict__ B) {
    int idx = blockIdx.x * blockDim.x + threadIdx.x;
    if (idx < 512 * 128) {
        int orow = idx >> 7, k = idx & 127;
        int sel = orow >> 7, r = orow & 127;
        const float* w = (sel == 0) ? wq : (sel == 1) ? wk : (sel == 2) ? wv : ws;
        Wh[idx] = __float2half_rn(w[r * 128 + k]);
    }
    if (idx < 512) {
        int sel = idx >> 7, r = idx & 127;
        const float* b = (sel == 0) ? bq : (sel == 1) ? bk : (sel == 2) ? bv : bs;
        B[idx] = b[r];
    }
}

__global__ void pack1(const float* __restrict__ w, const float* __restrict__ b,
                      __half* __restrict__ Wh, float* __restrict__ B) {
    int idx = blockIdx.x * blockDim.x + threadIdx.x;
    if (idx < 128 * 128) Wh[idx] = __float2half_rn(w[idx]);
    if (idx < 128) B[idx] = b[idx];
}

// ---------------- fp16 mma GEMM: X loaded once, loop over N-tiles ----------------
// Y[n,NT*64] = X[n,128] @ W^T + bias. Grid (mtiles); CTA tile 128 x (NT*64).
#define KH 136
#define GEMM_SMEM_H ((128 + 64) * KH * 2)        // 52224 B

template<bool RELU, bool WRITEKV, bool GATEDOT, int NT>
__global__ __launch_bounds__(256, 2)
void gemm_h(const float* __restrict__ X, int n,
            const __half* __restrict__ Wh, const float* __restrict__ bias,
            float* __restrict__ Y, const float* __restrict__ gw2d) {
    extern __shared__ __half sh[];
    __half* sX = sh;               // [128][KH]
    __half* sW = sh + 128 * KH;    // [64][KH]
    const int OUT = NT * 64;

    const int tid = threadIdx.x, wid = tid >> 5, lane = tid & 31;
    const int wm = wid & 3, wn = wid >> 2;
    const int row0 = blockIdx.x * 128;
    const int grp = lane >> 2, tg = lane & 3;

    // ---- X tile: f32 -> f16, loaded ONCE for all N-tiles ----
#pragma unroll
    for (int j = 0; j < 8; j++) {
        int idx = tid + 256 * j;
        int r = idx >> 4, c8 = idx & 15;
        int gr = row0 + r;
        float4 v0 = make_float4(0.f, 0.f, 0.f, 0.f);
        float4 v1 = make_float4(0.f, 0.f, 0.f, 0.f);
        if (gr < n) {
            v0 = *(const float4*)(X + (size_t)gr * 128 + c8 * 8);
            v1 = *(const float4*)(X + (size_t)gr * 128 + c8 * 8 + 4);
        }
        __half2 h0 = __floats2half2_rn(v0.x, v0.y);
        __half2 h1 = __floats2half2_rn(v0.z, v0.w);
        __half2 h2 = __floats2half2_rn(v1.x, v1.y);
        __half2 h3 = __floats2half2_rn(v1.z, v1.w);
        uint4 pk;
        pk.x = *(uint32_t*)&h0; pk.y = *(uint32_t*)&h1;
        pk.z = *(uint32_t*)&h2; pk.w = *(uint32_t*)&h3;
        *(uint4*)(sX + r * KH + c8 * 8) = pk;
    }

    float rp[2][2] = {{0.f, 0.f}, {0.f, 0.f}};   // gate partials (accumulate over tiles)

    for (int t = 0; t < NT; t++) {
        const int col0 = t * 64;
        // ---- W tile for this N-tile ----
#pragma unroll
        for (int j = 0; j < 4; j++) {
            int idx = tid + 256 * j;
            int r = idx >> 4, c8 = idx & 15;
            *(uint4*)(sW + r * KH + c8 * 8) =
                *(const uint4*)(Wh + (size_t)(col0 + r) * 128 + c8 * 8);
        }
        __syncthreads();

        float acc[2][4][4];
#pragma unroll
        for (int mt = 0; mt < 2; mt++)
#pragma unroll
            for (int nt = 0; nt < 4; nt++)
#pragma unroll
                for (int q = 0; q < 4; q++) acc[mt][nt][q] = 0.f;

#pragma unroll
        for (int ks = 0; ks < 8; ks++) {
            const int c = ks * 16 + 2 * tg;
            uint32_t a[2][4];
#pragma unroll
            for (int mt = 0; mt < 2; mt++) {
                const int r = wm * 32 + mt * 16 + grp;
                a[mt][0] = *(const uint32_t*)(sX + r * KH + c);
                a[mt][1] = *(const uint32_t*)(sX + (r + 8) * KH + c);
                a[mt][2] = *(const uint32_t*)(sX + r * KH + c + 8);
                a[mt][3] = *(const uint32_t*)(sX + (r + 8) * KH + c + 8);
            }
            uint32_t b[4][2];
#pragma unroll
            for (int nt = 0; nt < 4; nt++) {
                const int nr = wn * 32 + nt * 8 + grp;
                b[nt][0] = *(const uint32_t*)(sW + nr * KH + c);
                b[nt][1] = *(const uint32_t*)(sW + nr * KH + c + 8);
            }
#pragma unroll
            for (int mt = 0; mt < 2; mt++)
#pragma unroll
                for (int nt = 0; nt < 4; nt++) mma16(acc[mt][nt], a[mt], b[nt]);
        }

        // ---- epilogue for this tile ----
#pragma unroll
        for (int mt = 0; mt < 2; mt++) {
            const int gr = row0 + wm * 32 + mt * 16 + grp;
#pragma unroll
            for (int nt = 0; nt < 4; nt++) {
                const int col = col0 + wn * 32 + nt * 8 + 2 * tg;
                const float b0 = bias[col], b1 = bias[col + 1];
                float2 o1 = make_float2(acc[mt][nt][0] + b0, acc[mt][nt][1] + b1);
                float2 o2 = make_float2(acc[mt][nt][2] + b0, acc[mt][nt][3] + b1);
                if (RELU) {
                    o1.x = fmaxf(o1.x, 0.f); o1.y = fmaxf(o1.y, 0.f);
                    o2.x = fmaxf(o2.x, 0.f); o2.y = fmaxf(o2.y, 0.f);
                }
                if (GATEDOT) {
                    const float w0 = gw2d[col], w1 = gw2d[col + 1];
                    rp[mt][0] += o1.x * w0 + o1.y * w1;
                    rp[mt][1] += o2.x * w0 + o2.y * w1;
                } else {
                    const bool mid = WRITEKV && (col >= 128 && col < 384);
                    if (!mid) {
                        if (gr < n)     *(float2*)(Y + (size_t)gr * OUT + col) = o1;
                        if (gr + 8 < n) *(float2*)(Y + (size_t)(gr + 8) * OUT + col) = o2;
                    } else {
                        if (gr < n)
                            *(__half2*)(g_kv16 + (size_t)gr * 256 + (col - 128)) =
                                __floats2half2_rn(o1.x, o1.y);
                        if (gr + 8 < n)
                            *(__half2*)(g_kv16 + (size_t)(gr + 8) * 256 + (col - 128)) =
                                __floats2half2_rn(o2.x, o2.y);
                    }
                }
            }
        }
        __syncthreads();   // protect sW before next tile's load
    }

    if (GATEDOT) {
#pragma unroll
        for (int mt = 0; mt < 2; mt++)
#pragma unroll
            for (int h = 0; h < 2; h++) {
                float v = rp[mt][h];
                v += __shfl_xor_sync(0xffffffffu, v, 1);
                v += __shfl_xor_sync(0xffffffffu, v, 2);
                if (tg == 0) {
                    const int row = row0 + wm * 32 + mt * 16 + grp + h * 8;
                    if (row < n) atomicAdd(&g_gate[row], v);
                }
            }
    }
}

// ================= CSR build =================
__global__ void hist_zero(int n) {
    int i = blockIdx.x * blockDim.x + threadIdx.x;
    if (i < n) { g_cur[i] = 0; g_gate[i] = 0.f; }
}
__global__ void hist(const int* __restrict__ dst, int E) {
    int e = blockIdx.x * blockDim.x + threadIdx.x;
    if (e < E) atomicAdd(&g_cur[dst[e]], 1);
}
__global__ void scan_blocks(int n) {
    __shared__ int sm[256];
    int t = threadIdx.x;
    int i = blockIdx.x * 256 + t;
    int v = (i < n) ? g_cur[i] : 0;
    sm[t] = v;
    __syncthreads();
#pragma unroll
    for (int o = 1; o < 256; o <<= 1) {
        int x = (t >= o) ? sm[t - o] : 0;
        __syncthreads();
        sm[t] += x;
        __syncthreads();
    }
    if (i < n) g_off[i] = sm[t] - v;
    if (t == 255) g_bsums[blockIdx.x] = sm[255];
}
__global__ void scan_tops(int nblk) {
    __shared__ int sm[512];
    int t = threadIdx.x;
    int v = (t < nblk) ? g_bsums[t] : 0;
    sm[t] = v;
    __syncthreads();
#pragma unroll
    for (int o = 1; o < 512; o <<= 1) {
        int x = (t >= o) ? sm[t - o] : 0;
        __syncthreads();
        sm[t] += x;
        __syncthreads();
    }
    if (t < nblk) g_bsums[t] = sm[t] - v;
}
__global__ void scan_add(int n, int E) {
    int i = blockIdx.x * 256 + threadIdx.x;
    if (i < n) {
        int o = g_off[i] + g_bsums[blockIdx.x];
        g_off[i] = o;
        g_cur[i] = o;
    }
    if (i == 0) g_off[n] = E;
}
__global__ void fill_csr(const int* __restrict__ src, const int* __restrict__ dst, int E) {
    int e = blockIdx.x * blockDim.x + threadIdx.x;
    if (e >= E) return;
    int p = atomicAdd(&g_cur[dst[e]], 1);
    g_csrc[p] = src[e];
}

// ================= fused per-node attention (prefetch 8 loads, 4-edge pipeline) =================
__global__ __launch_bounds__(256, 6)
void node_attn(int n) {
    int node = (blockIdx.x * blockDim.x + threadIdx.x) >> 5;
    int lane = threadIdx.x & 31;
    if (node >= n) return;
    const float scale = 0.08838834764831845f;  // 1/sqrt(128)
    const float* base = g_qkvs + (size_t)node * 512;
    float4 q = *(const float4*)(base + lane * 4);
    q.x *= scale; q.y *= scale; q.z *= scale; q.w *= scale;

    int beg = g_off[node], end = g_off[node + 1];
    float4 acc = make_float4(0.f, 0.f, 0.f, 0.f);
    float sum = 0.f;

    int j = beg;
    for (; j + 4 <= end; j += 4) {
        const __half* r[4];
#pragma unroll
        for (int u = 0; u < 4; u++) r[u] = g_kv16 + (size_t)g_csrc[j + u] * 256;
        uint2 kk[4], vv[4];
#pragma unroll
        for (int u = 0; u < 4; u++) kk[u] = *(const uint2*)(r[u] + lane * 4);
#pragma unroll
        for (int u = 0; u < 4; u++) vv[u] = *(const uint2*)(r[u] + 128 + lane * 4);

        float d[4];
#pragma unroll
        for (int u = 0; u < 4; u++) {
            float2 a = __half22float2(*(const __half2*)&kk[u].x);
            float2 b = __half22float2(*(const __half2*)&kk[u].y);
            d[u] = q.x * a.x + q.y * a.y + q.z * b.x + q.w * b.y;
        }
#pragma unroll
        for (int o = 16; o; o >>= 1) {
#pragma unroll
            for (int u = 0; u < 4; u++) d[u] += __shfl_xor_sync(0xffffffffu, d[u], o);
        }
#pragma unroll
        for (int u = 0; u < 4; u++) {
            float e = __expf(d[u]);
            float2 va = __half22float2(*(const __half2*)&vv[u].x);
            float2 vb = __half22float2(*(const __half2*)&vv[u].y);
            acc.x += e * va.x; acc.y += e * va.y;
            acc.z += e * vb.x; acc.w += e * vb.y;
            sum += e;
        }
    }
    for (; j < end; j++) {
        const __half* r0 = g_kv16 + (size_t)g_csrc[j] * 256;
        uint2 kk = *(const uint2*)(r0 + lane * 4);
        uint2 vv = *(const uint2*)(r0 + 128 + lane * 4);
        float2 a = __half22float2(*(const __half2*)&kk.x);
        float2 b = __half22float2(*(const __half2*)&kk.y);
        float d0 = q.x * a.x + q.y * a.y + q.z * b.x + q.w * b.y;
#pragma unroll
        for (int o = 16; o; o >>= 1) d0 += __shfl_xor_sync(0xffffffffu, d0, o);
        float e0 = __expf(d0);
        float2 va = __half22float2(*(const __half2*)&vv.x);
        float2 vb = __half22float2(*(const __half2*)&vv.y);
        acc.x += e0 * va.x; acc.y += e0 * va.y;
        acc.z += e0 * vb.x; acc.w += e0 * vb.y;
        sum += e0;
    }

    float inv = (end > beg) ? (1.f / sum) : 0.f;
    float4 skip = *(const float4*)(base + 384 + lane * 4);
    float4 o;
    o.x = fmaxf(acc.x * inv + skip.x, 0.f);
    o.y = fmaxf(acc.y * inv + skip.y, 0.f);
    o.z = fmaxf(acc.z * inv + skip.z, 0.f);
    o.w = fmaxf(acc.w * inv + skip.w, 0.f);
    *(float4*)(g_h + (size_t)node * 128 + lane * 4) = o;
}

// ---------------- graph-level ----------------
__global__ void init_graph() {
    int i = blockIdx.x * blockDim.x + threadIdx.x;
    if (i < GGR * 128) g_pool[i] = 0.f;
    if (i < GGR) g_gs[i] = 0.f;
}

__global__ void node_exp(const float* __restrict__ gb2, const int* __restrict__ batch, int n) {
    int i = blockIdx.x * blockDim.x + threadIdx.x;
    if (i >= n) return;
    float ev = __expf(g_gate[i] + gb2[0]);
    g_gate[i] = ev;
    atomicAdd(&g_gs[batch[i]], ev);
}

#define POOL_CHUNK 512
__global__ void pool_kernel(const int* __restrict__ batch, int n) {
    int d = threadIdx.x;
    int n0 = blockIdx.x * POOL_CHUNK;
    int n1 = min(n0 + POOL_CHUNK, n);
    if (n0 >= n) return;
    int curb = batch[n0];
    float acc = 0.f;
    for (int node = n0; node < n1; node++) {
        int b = batch[node];
        if (b != curb) {
            atomicAdd(&g_pool[curb * 128 + d], acc);
            acc = 0.f; curb = b;
        }
        float wgt = g_gate[node] / g_gs[b];
        acc += wgt * g_h[(size_t)node * 128 + d];
    }
    atomicAdd(&g_pool[curb * 128 + d], acc);
}

__global__ void classifier(const float* __restrict__ cw, const float* __restrict__ cb,
                           float* __restrict__ out) {
    int i = threadIdx.x;
    if (i >= GGR * 10) return;
    int g = i / 10, c = i % 10;
    float a = cb[c];
#pragma unroll 16
    for (int k = 0; k < 128; k++) a += g_pool[g * 128 + k] * cw[c * 128 + k];
    out[i] = a;
}

// ---------------- host orchestration ----------------
extern "C" void kernel_launch(void* const* d_in, const int* in_sizes, int n_in,
                              void* d_out, int out_size) {
    const float* x   = (const float*)d_in[0];
    const int* eidx  = (const int*)d_in[1];
    const int* batch = (const int*)d_in[2];
    const float *wq1 = (const float*)d_in[3],  *bq1 = (const float*)d_in[4];
    const float *wk1 = (const float*)d_in[5],  *bk1 = (const float*)d_in[6];
    const float *wv1 = (const float*)d_in[7],  *bv1 = (const float*)d_in[8];
    const float *ws1 = (const float*)d_in[9],  *bs1 = (const float*)d_in[10];
    const float *wq2 = (const float*)d_in[11], *bq2 = (const float*)d_in[12];
    const float *wk2 = (const float*)d_in[13], *bk2 = (const float*)d_in[14];
    const float *wv2 = (const float*)d_in[15], *bv2 = (const float*)d_in[16];
    const float *ws2 = (const float*)d_in[17], *bs2 = (const float*)d_in[18];
    const float *gw1 = (const float*)d_in[19], *gb1 = (const float*)d_in[20];
    const float *gw2 = (const float*)d_in[21], *gb2 = (const float*)d_in[22];
    const float *cw  = (const float*)d_in[23], *cb  = (const float*)d_in[24];
    float* out = (float*)d_out;

    const int n = in_sizes[0] / 128;
    const int E = in_sizes[1] / 2;
    const int* src = eidx;
    const int* dst = eidx + E;

    static float* p_qkvs = nullptr; static float* p_h = nullptr;
    static __half *p_Wh1 = nullptr, *p_Wh2 = nullptr, *p_Whg = nullptr;
    static float  *p_B1 = nullptr,  *p_B2 = nullptr,  *p_Bg = nullptr;
    if (!p_qkvs) {
        cudaGetSymbolAddress((void**)&p_qkvs, g_qkvs);
        cudaGetSymbolAddress((void**)&p_h,    g_h);
        cudaGetSymbolAddress((void**)&p_Wh1,  g_Wh1);
        cudaGetSymbolAddress((void**)&p_Wh2,  g_Wh2);
        cudaGetSymbolAddress((void**)&p_Whg,  g_Whg);
        cudaGetSymbolAddress((void**)&p_B1,   g_B1);
        cudaGetSymbolAddress((void**)&p_B2,   g_B2);
        cudaGetSymbolAddress((void**)&p_Bg,   g_Bg);
        cudaFuncSetAttribute((const void*)gemm_h<false, true, false, 8>,
                             cudaFuncAttributeMaxDynamicSharedMemorySize, GEMM_SMEM_H);
        cudaFuncSetAttribute((const void*)gemm_h<true, false, true, 2>,
                             cudaFuncAttributeMaxDynamicSharedMemorySize, GEMM_SMEM_H);
    }

    const int nwb  = (n + 255) / 256;
    const int etb  = (E + 255) / 256;
    const int nblk = (n + 255) / 256;
    const int nab  = (n * 32 + 255) / 256;      // 1 warp/node
    const int mtiles = (n + 127) / 128;

    // ---- weight packs + graph init up front ----
    pack4<<<(512 * 128 + 255) / 256, 256>>>(wq1, bq1, wk1, bk1, wv1, bv1, ws1, bs1,
                                            p_Wh1, p_B1);
    pack4<<<(512 * 128 + 255) / 256, 256>>>(wq2, bq2, wk2, bk2, wv2, bv2, ws2, bs2,
                                            p_Wh2, p_B2);
    pack1<<<(128 * 128 + 255) / 256, 256>>>(gw1, gb1, p_Whg, p_Bg);
    init_graph<<<32, 256>>>();

    // ---- CSR build (also zeroes g_gate) ----
    hist_zero<<<nwb, 256>>>(n);
    hist<<<etb, 256>>>(dst, E);
    scan_blocks<<<nblk, 256>>>(n);
    scan_tops<<<1, 512>>>(nblk);
    scan_add<<<nblk, 256>>>(n, E);
    fill_csr<<<etb, 256>>>(src, dst, E);

    // ---- Layer 1 ----
    gemm_h<false, true, false, 8><<<mtiles, 256, GEMM_SMEM_H>>>(x, n, p_Wh1, p_B1,
                                                                p_qkvs, nullptr);
    node_attn<<<nab, 256>>>(n);

    // ---- Layer 2 ----
    gemm_h<false, true, false, 8><<<mtiles, 256, GEMM_SMEM_H>>>(p_h, n, p_Wh2, p_B2,
                                                                p_qkvs, nullptr);
    node_attn<<<nab, 256>>>(n);

    // ---- Global attention (fused gate dot in GEMM epilogue) ----
    gemm_h<true, false, true, 2><<<mtiles, 256, GEMM_SMEM_H>>>(p_h, n, p_Whg, p_Bg,
                                                               nullptr, gw2);
    node_exp<<<nwb, 256>>>(gb2, batch, n);
    pool_kernel<<<(n + POOL_CHUNK - 1) / POOL_CHUNK, 128>>>(batch, n);

    // ---- Classifier ----
    classifier<<<1, 1024>>>(cw, cb, out);
}

// round 12
// speedup vs baseline: 1.4083x; 1.0262x over previous
#include <cuda_runtime.h>
#include <cuda_fp16.h>
#include <cstdint>

// Problem constants
#define NN 100000
#define EE 1600000
#define GGR 64

// ---------------- static device scratch (all intermediates fp16) ----------------
__device__ __half   g_q16 [(size_t)NN * 128];  // q, pre-scaled by 1/sqrt(128)
__device__ __half   g_kv16[(size_t)NN * 256];  // k[0:128) v[128:256)
__device__ __half   g_sk16[(size_t)NN * 128];  // skip connection
__device__ __half   g_h16 [(size_t)NN * 128];  // layer output
__device__ float    g_gate[NN];                // raw gate logit accum -> exp value
__device__ float    g_pool[GGR * 128];
__device__ float    g_gs[GGR];
__device__ __half   g_Wh1[512 * 128];
__device__ __half   g_Wh2[512 * 128];
__device__ __half   g_Whg[128 * 128];
__device__ float    g_B1[512];
__device__ float    g_B2[512];
__device__ float    g_Bg[128];
// CSR (dst-sorted adjacency)
__device__ int      g_off[NN + 1];
__device__ int      g_cur[NN];
__device__ int      g_csrc[EE];
__device__ int      g_bsums[512];

#define QSCALE 0.08838834764831845f   // 1/sqrt(128)

// ---------------- fp16 mma ----------------
__device__ __forceinline__ void mma16(float* d, const uint32_t* a, const uint32_t* b) {
    asm volatile("mma.sync.aligned.m16n8k16.row.col.f32.f16.f16.f32 "
        "{%0,%1,%2,%3}, {%4,%5,%6,%7}, {%8,%9}, {%0,%1,%2,%3};"
        : "+f"(d[0]), "+f"(d[1]), "+f"(d[2]), "+f"(d[3])
        : "r"(a[0]), "r"(a[1]), "r"(a[2]), "r"(a[3]), "r"(b[0]), "r"(b[1]));
}

// ---------------- weight packing (fp16); wq/bq pre-scaled by 1/sqrt(128) ----------------
__global__ void pack4(const float* __restrict__ wq, const float* __restrict__ bq,
                      const float* __restrict__ wk, const float* __restrict__ bk,
                      const float* __restrict__ wv, const float* __restrict__ bv,
                      const float* __restrict__ ws, const float* __restrict__ bs,
                      __half* __restrict__ Wh, float* __restrict__ B) {
    int idx = blockIdx.x * blockDim.x + threadIdx.x;
    if (idx < 512 * 128) {
        int orow = idx >> 7, k = idx & 127;
        int sel = orow >> 7, r = orow & 127;
        const float* w = (sel == 0) ? wq : (sel == 1) ? wk : (sel == 2) ? wv : ws;
        float v = w[r * 128 + k];
        if (sel == 0) v *= QSCALE;
        Wh[idx] = __float2half_rn(v);
    }
    if (idx < 512) {
        int sel = idx >> 7, r = idx & 127;
        const float* b = (sel == 0) ? bq : (sel == 1) ? bk : (sel == 2) ? bv : bs;
        float v = b[r];
        if (sel == 0) v *= QSCALE;
        B[idx] = v;
    }
}

__global__ void pack1(const float* __restrict__ w, const float* __restrict__ b,
                      __half* __restrict__ Wh, float* __restrict__ B) {
    int idx = blockIdx.x * blockDim.x + threadIdx.x;
    if (idx < 128 * 128) Wh[idx] = __float2half_rn(w[idx]);
    if (idx < 128) B[idx] = b[idx];
}

// ---------------- fp16 mma GEMM: X loaded once, loop over N-tiles ----------------
// GATEDOT=false (NT=8): epilogue writes q16/kv16/sk16 (all fp16).
// GATEDOT=true  (NT=2): relu + dot with gw2, atomicAdd into g_gate. No stores.
#define KH 136
#define GEMM_SMEM_H ((128 + 64) * KH * 2)        // 52224 B

template<bool GATEDOT, int NT, typename TIN>
__global__ __launch_bounds__(256, 2)
void gemm_h(const TIN* __restrict__ X, int n,
            const __half* __restrict__ Wh, const float* __restrict__ bias,
            const float* __restrict__ gw2d) {
    extern __shared__ __half sh[];
    __half* sX = sh;               // [128][KH]
    __half* sW = sh + 128 * KH;    // [64][KH]

    const int tid = threadIdx.x, wid = tid >> 5, lane = tid & 31;
    const int wm = wid & 3, wn = wid >> 2;
    const int row0 = blockIdx.x * 128;
    const int grp = lane >> 2, tg = lane & 3;

    // ---- X tile loaded ONCE ----
#pragma unroll
    for (int j = 0; j < 8; j++) {
        int idx = tid + 256 * j;
        int r = idx >> 4, c8 = idx & 15;
        int gr = row0 + r;
        uint4 pk = make_uint4(0u, 0u, 0u, 0u);
        if (gr < n) {
            if (sizeof(TIN) == 4) {
                const float* Xf = (const float*)X;
                float4 v0 = *(const float4*)(Xf + (size_t)gr * 128 + c8 * 8);
                float4 v1 = *(const float4*)(Xf + (size_t)gr * 128 + c8 * 8 + 4);
                __half2 h0 = __floats2half2_rn(v0.x, v0.y);
                __half2 h1 = __floats2half2_rn(v0.z, v0.w);
                __half2 h2 = __floats2half2_rn(v1.x, v1.y);
                __half2 h3 = __floats2half2_rn(v1.z, v1.w);
                pk.x = *(uint32_t*)&h0; pk.y = *(uint32_t*)&h1;
                pk.z = *(uint32_t*)&h2; pk.w = *(uint32_t*)&h3;
            } else {
                const __half* Xh = (const __half*)X;
                pk = *(const uint4*)(Xh + (size_t)gr * 128 + c8 * 8);
            }
        }
        *(uint4*)(sX + r * KH + c8 * 8) = pk;
    }

    float rp[2][2] = {{0.f, 0.f}, {0.f, 0.f}};

    for (int t = 0; t < NT; t++) {
        const int col0 = t * 64;
#pragma unroll
        for (int j = 0; j < 4; j++) {
            int idx = tid + 256 * j;
            int r = idx >> 4, c8 = idx & 15;
            *(uint4*)(sW + r * KH + c8 * 8) =
                *(const uint4*)(Wh + (size_t)(col0 + r) * 128 + c8 * 8);
        }
        __syncthreads();

        float acc[2][4][4];
#pragma unroll
        for (int mt = 0; mt < 2; mt++)
#pragma unroll
            for (int nt = 0; nt < 4; nt++)
#pragma unroll
                for (int q = 0; q < 4; q++) acc[mt][nt][q] = 0.f;

#pragma unroll
        for (int ks = 0; ks < 8; ks++) {
            const int c = ks * 16 + 2 * tg;
            uint32_t a[2][4];
#pragma unroll
            for (int mt = 0; mt < 2; mt++) {
                const int r = wm * 32 + mt * 16 + grp;
                a[mt][0] = *(const uint32_t*)(sX + r * KH + c);
                a[mt][1] = *(const uint32_t*)(sX + (r + 8) * KH + c);
                a[mt][2] = *(const uint32_t*)(sX + r * KH + c + 8);
                a[mt][3] = *(const uint32_t*)(sX + (r + 8) * KH + c + 8);
            }
            uint32_t b[4][2];
#pragma unroll
            for (int nt = 0; nt < 4; nt++) {
                const int nr = wn * 32 + nt * 8 + grp;
                b[nt][0] = *(const uint32_t*)(sW + nr * KH + c);
                b[nt][1] = *(const uint32_t*)(sW + nr * KH + c + 8);
            }
#pragma unroll
            for (int mt = 0; mt < 2; mt++)
#pragma unroll
                for (int nt = 0; nt < 4; nt++) mma16(acc[mt][nt], a[mt], b[nt]);
        }

        // ---- epilogue for this tile ----
#pragma unroll
        for (int mt = 0; mt < 2; mt++) {
            const int gr = row0 + wm * 32 + mt * 16 + grp;
#pragma unroll
            for (int nt = 0; nt < 4; nt++) {
                const int col = col0 + wn * 32 + nt * 8 + 2 * tg;
                const float b0 = bias[col], b1 = bias[col + 1];
                float2 o1 = make_float2(acc[mt][nt][0] + b0, acc[mt][nt][1] + b1);
                float2 o2 = make_float2(acc[mt][nt][2] + b0, acc[mt][nt][3] + b1);
                if (GATEDOT) {
                    o1.x = fmaxf(o1.x, 0.f); o1.y = fmaxf(o1.y, 0.f);
                    o2.x = fmaxf(o2.x, 0.f); o2.y = fmaxf(o2.y, 0.f);
                    const float w0 = gw2d[col], w1 = gw2d[col + 1];
                    rp[mt][0] += o1.x * w0 + o1.y * w1;
                    rp[mt][1] += o2.x * w0 + o2.y * w1;
                } else {
                    // route by tile: t<2 -> q16, t<6 -> kv16, else sk16 (uniform per CTA)
                    __half* dst0;
                    __half* dst1;
                    if (t < 2) {
                        dst0 = g_q16 + (size_t)gr * 128 + col;
                        dst1 = g_q16 + (size_t)(gr + 8) * 128 + col;
                    } else if (t < 6) {
                        dst0 = g_kv16 + (size_t)gr * 256 + (col - 128);
                        dst1 = g_kv16 + (size_t)(gr + 8) * 256 + (col - 128);
                    } else {
                        dst0 = g_sk16 + (size_t)gr * 128 + (col - 384);
                        dst1 = g_sk16 + (size_t)(gr + 8) * 128 + (col - 384);
                    }
                    if (gr < n)     *(__half2*)dst0 = __floats2half2_rn(o1.x, o1.y);
                    if (gr + 8 < n) *(__half2*)dst1 = __floats2half2_rn(o2.x, o2.y);
                }
            }
        }
        __syncthreads();   // protect sW before next tile's load
    }

    if (GATEDOT) {
#pragma unroll
        for (int mt = 0; mt < 2; mt++)
#pragma unroll
            for (int h = 0; h < 2; h++) {
                float v = rp[mt][h];
                v += __shfl_xor_sync(0xffffffffu, v, 1);
                v += __shfl_xor_sync(0xffffffffu, v, 2);
                if (tg == 0) {
                    const int row = row0 + wm * 32 + mt * 16 + grp + h * 8;
                    if (row < n) atomicAdd(&g_gate[row], v);
                }
            }
    }
}

// ================= CSR build =================
__global__ void hist_zero(int n) {
    int i = blockIdx.x * blockDim.x + threadIdx.x;
    if (i < n) { g_cur[i] = 0; g_gate[i] = 0.f; }
}
__global__ void hist(const int* __restrict__ dst, int E) {
    int e = blockIdx.x * blockDim.x + threadIdx.x;
    if (e < E) atomicAdd(&g_cur[dst[e]], 1);
}
__global__ void scan_blocks(int n) {
    __shared__ int sm[256];
    int t = threadIdx.x;
    int i = blockIdx.x * 256 + t;
    int v = (i < n) ? g_cur[i] : 0;
    sm[t] = v;
    __syncthreads();
#pragma unroll
    for (int o = 1; o < 256; o <<= 1) {
        int x = (t >= o) ? sm[t - o] : 0;
        __syncthreads();
        sm[t] += x;
        __syncthreads();
    }
    if (i < n) g_off[i] = sm[t] - v;
    if (t == 255) g_bsums[blockIdx.x] = sm[255];
}
__global__ void scan_tops(int nblk) {
    __shared__ int sm[512];
    int t = threadIdx.x;
    int v = (t < nblk) ? g_bsums[t] : 0;
    sm[t] = v;
    __syncthreads();
#pragma unroll
    for (int o = 1; o < 512; o <<= 1) {
        int x = (t >= o) ? sm[t - o] : 0;
        __syncthreads();
        sm[t] += x;
        __syncthreads();
    }
    if (t < nblk) g_bsums[t] = sm[t] - v;
}
__global__ void scan_add(int n, int E) {
    int i = blockIdx.x * 256 + threadIdx.x;
    if (i < n) {
        int o = g_off[i] + g_bsums[blockIdx.x];
        g_off[i] = o;
        g_cur[i] = o;
    }
    if (i == 0) g_off[n] = E;
}
__global__ void fill_csr(const int* __restrict__ src, const int* __restrict__ dst, int E) {
    int e = blockIdx.x * blockDim.x + threadIdx.x;
    if (e >= E) return;
    int p = atomicAdd(&g_cur[dst[e]], 1);
    g_csrc[p] = src[e];
}

// ================= fused per-node attention (fp16 everywhere) =================
__global__ __launch_bounds__(256, 6)
void node_attn(int n) {
    int node = (blockIdx.x * blockDim.x + threadIdx.x) >> 5;
    int lane = threadIdx.x & 31;
    if (node >= n) return;

    // q: pre-scaled fp16
    uint2 qp = *(const uint2*)(g_q16 + (size_t)node * 128 + lane * 4);
    float2 q01 = __half22float2(*(const __half2*)&qp.x);
    float2 q23 = __half22float2(*(const __half2*)&qp.y);
    float4 q = make_float4(q01.x, q01.y, q23.x, q23.y);

    int beg = g_off[node], end = g_off[node + 1];
    float4 acc = make_float4(0.f, 0.f, 0.f, 0.f);
    float sum = 0.f;

    int j = beg;
    for (; j + 4 <= end; j += 4) {
        const __half* r[4];
#pragma unroll
        for (int u = 0; u < 4; u++) r[u] = g_kv16 + (size_t)g_csrc[j + u] * 256;
        uint2 kk[4], vv[4];
#pragma unroll
        for (int u = 0; u < 4; u++) kk[u] = *(const uint2*)(r[u] + lane * 4);
#pragma unroll
        for (int u = 0; u < 4; u++) vv[u] = *(const uint2*)(r[u] + 128 + lane * 4);

        float d[4];
#pragma unroll
        for (int u = 0; u < 4; u++) {
            float2 a = __half22float2(*(const __half2*)&kk[u].x);
            float2 b = __half22float2(*(const __half2*)&kk[u].y);
            d[u] = q.x * a.x + q.y * a.y + q.z * b.x + q.w * b.y;
        }
#pragma unroll
        for (int o = 16; o; o >>= 1) {
#pragma unroll
            for (int u = 0; u < 4; u++) d[u] += __shfl_xor_sync(0xffffffffu, d[u], o);
        }
#pragma unroll
        for (int u = 0; u < 4; u++) {
            float e = __expf(d[u]);
            float2 va = __half22float2(*(const __half2*)&vv[u].x);
            float2 vb = __half22float2(*(const __half2*)&vv[u].y);
            acc.x += e * va.x; acc.y += e * va.y;
            acc.z += e * vb.x; acc.w += e * vb.y;
            sum += e;
        }
    }
    for (; j < end; j++) {
        const __half* r0 = g_kv16 + (size_t)g_csrc[j] * 256;
        uint2 kk = *(const uint2*)(r0 + lane * 4);
        uint2 vv = *(const uint2*)(r0 + 128 + lane * 4);
        float2 a = __half22float2(*(const __half2*)&kk.x);
        float2 b = __half22float2(*(const __half2*)&kk.y);
        float d0 = q.x * a.x + q.y * a.y + q.z * b.x + q.w * b.y;
#pragma unroll
        for (int o = 16; o; o >>= 1) d0 += __shfl_xor_sync(0xffffffffu, d0, o);
        float e0 = __expf(d0);
        float2 va = __half22float2(*(const __half2*)&vv.x);
        float2 vb = __half22float2(*(const __half2*)&vv.y);
        acc.x += e0 * va.x; acc.y += e0 * va.y;
        acc.z += e0 * vb.x; acc.w += e0 * vb.y;
        sum += e0;
    }

    float inv = (end > beg) ? (1.f / sum) : 0.f;
    uint2 sp = *(const uint2*)(g_sk16 + (size_t)node * 128 + lane * 4);
    float2 s01 = __half22float2(*(const __half2*)&sp.x);
    float2 s23 = __half22float2(*(const __half2*)&sp.y);
    float ox = fmaxf(acc.x * inv + s01.x, 0.f);
    float oy = fmaxf(acc.y * inv + s01.y, 0.f);
    float oz = fmaxf(acc.z * inv + s23.x, 0.f);
    float ow = fmaxf(acc.w * inv + s23.y, 0.f);
    uint2 outp;
    *(__half2*)&outp.x = __floats2half2_rn(ox, oy);
    *(__half2*)&outp.y = __floats2half2_rn(oz, ow);
    *(uint2*)(g_h16 + (size_t)node * 128 + lane * 4) = outp;
}

// ---------------- graph-level ----------------
__global__ void init_graph() {
    int i = blockIdx.x * blockDim.x + threadIdx.x;
    if (i < GGR * 128) g_pool[i] = 0.f;
    if (i < GGR) g_gs[i] = 0.f;
}

__global__ void node_exp(const float* __restrict__ gb2, const int* __restrict__ batch, int n) {
    int i = blockIdx.x * blockDim.x + threadIdx.x;
    if (i >= n) return;
    float ev = __expf(g_gate[i] + gb2[0]);
    g_gate[i] = ev;
    atomicAdd(&g_gs[batch[i]], ev);
}

#define POOL_CHUNK 512
__global__ void pool_kernel(const int* __restrict__ batch, int n) {
    int d = threadIdx.x;
    int n0 = blockIdx.x * POOL_CHUNK;
    int n1 = min(n0 + POOL_CHUNK, n);
    if (n0 >= n) return;
    int curb = batch[n0];
    float acc = 0.f;
    for (int node = n0; node < n1; node++) {
        int b = batch[node];
        if (b != curb) {
            atomicAdd(&g_pool[curb * 128 + d], acc);
            acc = 0.f; curb = b;
        }
        float wgt = g_gate[node] / g_gs[b];
        acc += wgt * __half2float(g_h16[(size_t)node * 128 + d]);
    }
    atomicAdd(&g_pool[curb * 128 + d], acc);
}

__global__ void classifier(const float* __restrict__ cw, const float* __restrict__ cb,
                           float* __restrict__ out) {
    int i = threadIdx.x;
    if (i >= GGR * 10) return;
    int g = i / 10, c = i % 10;
    float a = cb[c];
#pragma unroll 16
    for (int k = 0; k < 128; k++) a += g_pool[g * 128 + k] * cw[c * 128 + k];
    out[i] = a;
}

// ---------------- host orchestration ----------------
extern "C" void kernel_launch(void* const* d_in, const int* in_sizes, int n_in,
                              void* d_out, int out_size) {
    const float* x   = (const float*)d_in[0];
    const int* eidx  = (const int*)d_in[1];
    const int* batch = (const int*)d_in[2];
    const float *wq1 = (const float*)d_in[3],  *bq1 = (const float*)d_in[4];
    const float *wk1 = (const float*)d_in[5],  *bk1 = (const float*)d_in[6];
    const float *wv1 = (const float*)d_in[7],  *bv1 = (const float*)d_in[8];
    const float *ws1 = (const float*)d_in[9],  *bs1 = (const float*)d_in[10];
    const float *wq2 = (const float*)d_in[11], *bq2 = (const float*)d_in[12];
    const float *wk2 = (const float*)d_in[13], *bk2 = (const float*)d_in[14];
    const float *wv2 = (const float*)d_in[15], *bv2 = (const float*)d_in[16];
    const float *ws2 = (const float*)d_in[17], *bs2 = (const float*)d_in[18];
    const float *gw1 = (const float*)d_in[19], *gb1 = (const float*)d_in[20];
    const float *gw2 = (const float*)d_in[21], *gb2 = (const float*)d_in[22];
    const float *cw  = (const float*)d_in[23], *cb  = (const float*)d_in[24];
    float* out = (float*)d_out;

    const int n = in_sizes[0] / 128;
    const int E = in_sizes[1] / 2;
    const int* src = eidx;
    const int* dst = eidx + E;

    static __half *p_h16 = nullptr, *p_Wh1 = nullptr, *p_Wh2 = nullptr, *p_Whg = nullptr;
    static float  *p_B1 = nullptr,  *p_B2 = nullptr,  *p_Bg = nullptr;
    if (!p_h16) {
        cudaGetSymbolAddress((void**)&p_h16,  g_h16);
        cudaGetSymbolAddress((void**)&p_Wh1,  g_Wh1);
        cudaGetSymbolAddress((void**)&p_Wh2,  g_Wh2);
        cudaGetSymbolAddress((void**)&p_Whg,  g_Whg);
        cudaGetSymbolAddress((void**)&p_B1,   g_B1);
        cudaGetSymbolAddress((void**)&p_B2,   g_B2);
        cudaGetSymbolAddress((void**)&p_Bg,   g_Bg);
        cudaFuncSetAttribute((const void*)gemm_h<false, 8, float>,
                             cudaFuncAttributeMaxDynamicSharedMemorySize, GEMM_SMEM_H);
        cudaFuncSetAttribute((const void*)gemm_h<false, 8, __half>,
                             cudaFuncAttributeMaxDynamicSharedMemorySize, GEMM_SMEM_H);
        cudaFuncSetAttribute((const void*)gemm_h<true, 2, __half>,
                             cudaFuncAttributeMaxDynamicSharedMemorySize, GEMM_SMEM_H);
    }

    const int nwb  = (n + 255) / 256;
    const int etb  = (E + 255) / 256;
    const int nblk = (n + 255) / 256;
    const int nab  = (n * 32 + 255) / 256;      // 1 warp/node
    const int mtiles = (n + 127) / 128;

    // ---- weight packs + graph init up front ----
    pack4<<<(512 * 128 + 255) / 256, 256>>>(wq1, bq1, wk1, bk1, wv1, bv1, ws1, bs1,
                                            p_Wh1, p_B1);
    pack4<<<(512 * 128 + 255) / 256, 256>>>(wq2, bq2, wk2, bk2, wv2, bv2, ws2, bs2,
                                            p_Wh2, p_B2);
    pack1<<<(128 * 128 + 255) / 256, 256>>>(gw1, gb1, p_Whg, p_Bg);
    init_graph<<<32, 256>>>();

    // ---- CSR build (also zeroes g_gate) ----
    hist_zero<<<nwb, 256>>>(n);
    hist<<<etb, 256>>>(dst, E);
    scan_blocks<<<nblk, 256>>>(n);
    scan_tops<<<1, 512>>>(nblk);
    scan_add<<<nblk, 256>>>(n, E);
    fill_csr<<<etb, 256>>>(src, dst, E);

    // ---- Layer 1 (fp32 input) ----
    gemm_h<false, 8, float><<<mtiles, 256, GEMM_SMEM_H>>>(x, n, p_Wh1, p_B1, nullptr);
    node_attn<<<nab, 256>>>(n);

    // ---- Layer 2 (fp16 input) ----
    gemm_h<false, 8, __half><<<mtiles, 256, GEMM_SMEM_H>>>(p_h16, n, p_Wh2, p_B2, nullptr);
    node_attn<<<nab, 256>>>(n);

    // ---- Global attention (fused gate dot, fp16 input) ----
    gemm_h<true, 2, __half><<<mtiles, 256, GEMM_SMEM_H>>>(p_h16, n, p_Whg, p_Bg, gw2);
    node_exp<<<nwb, 256>>>(gb2, batch, n);
    pool_kernel<<<(n + POOL_CHUNK - 1) / POOL_CHUNK, 128>>>(batch, n);

    // ---- Classifier ----
    classifier<<<1, 1024>>>(cw, cb, out);
}